// round 13
// baseline (speedup 1.0000x reference)
#include <cuda_runtime.h>
#include <cuda_bf16.h>
#include <math.h>
#include <stdint.h>

typedef __nv_bfloat16 bf16;

// ---------------- problem constants ----------------
constexpr int B_  = 128;
constexpr int T_  = 69;
constexpr int S_  = 77;
constexpr int D_  = 512;
constexpr int H_  = 8;
constexpr int DH_ = 64;
constexpr int NL_ = 12;
constexpr int FF_ = 2048;
constexpr int NP_ = 8;
constexpr int DG_ = 6;
constexpr int DS_ = 6;
constexpr int MROWS = B_ * S_;   // 9856 = 77 * 128
constexpr int QKVN  = 3 * D_;    // 1536

// ---------------- scratch (device globals; no runtime alloc) ----------------
__device__ __align__(128) float g_x  [MROWS * D_];
__device__ __align__(128) bf16  g_hhi[MROWS * D_];
__device__ __align__(128) bf16  g_hlo[MROWS * D_];
__device__ __align__(128) float g_qkv[MROWS * QKVN];
__device__ __align__(128) bf16  g_ohi[MROWS * D_];
__device__ __align__(128) bf16  g_olo[MROWS * D_];
__device__ __align__(128) bf16  g_fhi[MROWS * FF_];
__device__ __align__(128) bf16  g_flo[MROWS * FF_];

// transposed weight splits [layer][N][K] (K-major)
__device__ __align__(128) bf16  w_qkv_hi[NL_ * QKVN * D_];
__device__ __align__(128) bf16  w_qkv_lo[NL_ * QKVN * D_];
__device__ __align__(128) bf16  w_o_hi  [NL_ * D_ * D_];
__device__ __align__(128) bf16  w_o_lo  [NL_ * D_ * D_];
__device__ __align__(128) bf16  w_1_hi  [NL_ * FF_ * D_];
__device__ __align__(128) bf16  w_1_lo  [NL_ * FF_ * D_];
__device__ __align__(128) bf16  w_2_hi  [NL_ * D_ * FF_];
__device__ __align__(128) bf16  w_2_lo  [NL_ * D_ * FF_];
__device__ float g_bqkv  [NL_ * QKVN];

// ---------------- PTX helpers ----------------
__device__ __forceinline__ uint32_t smem_u32(const void* p) {
    uint32_t a;
    asm("{ .reg .u64 t; cvta.to.shared.u64 t, %1; cvt.u32.u64 %0, t; }" : "=r"(a) : "l"(p));
    return a;
}

#define CP16(saddr, gptr) \
    asm volatile("cp.async.cg.shared.global [%0], [%1], 16;" :: "r"(saddr), "l"(gptr) : "memory")
#define CP_COMMIT() asm volatile("cp.async.commit_group;" ::: "memory")
#define CP_WAIT1()  asm volatile("cp.async.wait_group 1;" ::: "memory")
#define CP_WAIT0()  asm volatile("cp.async.wait_group 0;" ::: "memory")

__device__ __forceinline__ void ldsm4(uint32_t* r, uint32_t addr) {
    asm volatile("ldmatrix.sync.aligned.m8n8.x4.shared.b16 {%0,%1,%2,%3}, [%4];"
                 : "=r"(r[0]), "=r"(r[1]), "=r"(r[2]), "=r"(r[3]) : "r"(addr));
}

__device__ __forceinline__ void mma16816(float* d, const uint32_t* a, const uint32_t* b) {
    asm volatile(
        "mma.sync.aligned.m16n8k16.row.col.f32.bf16.bf16.f32 "
        "{%0,%1,%2,%3}, {%4,%5,%6,%7}, {%8,%9}, {%0,%1,%2,%3};"
        : "+f"(d[0]), "+f"(d[1]), "+f"(d[2]), "+f"(d[3])
        : "r"(a[0]), "r"(a[1]), "r"(a[2]), "r"(a[3]), "r"(b[0]), "r"(b[1]));
}

// ---------------- unified preprocessing (1 launch) ----------------
__device__ __forceinline__ void tsplit_tile(const float* src, bf16* hi, bf16* lo,
                                            int K, int N, int n0, int k0, float scale) {
    __shared__ float t[32][33];
    int lx = threadIdx.x & 31, ly = threadIdx.x >> 5;
    #pragma unroll
    for (int i = ly; i < 32; i += 8)
        t[i][lx] = src[(size_t)(k0 + i) * N + n0 + lx];
    __syncthreads();
    #pragma unroll
    for (int i = ly; i < 32; i += 8) {
        float v = t[lx][i] * scale;
        size_t o = (size_t)(n0 + i) * K + k0 + lx;
        bf16 h = __float2bfloat16(v);
        hi[o] = h;
        lo[o] = __float2bfloat16(v - __bfloat162float(h));
    }
}

__global__ void __launch_bounds__(256)
prep_kernel(const float* __restrict__ Wq, const float* __restrict__ Wk,
            const float* __restrict__ Wv, const float* __restrict__ Wo,
            const float* __restrict__ W1, const float* __restrict__ W2,
            const float* __restrict__ bq, const float* __restrict__ bk,
            const float* __restrict__ bv,
            bf16* __restrict__ wqh, bf16* __restrict__ wql,
            bf16* __restrict__ woh, bf16* __restrict__ wol,
            bf16* __restrict__ w1h, bf16* __restrict__ w1l,
            bf16* __restrict__ w2h, bf16* __restrict__ w2l,
            float* __restrict__ bqkv) {
    int grp = blockIdx.y, layer = blockIdx.z, x = blockIdx.x;
    if (grp < 4) {
        if (x >= 256) return;
        int nt = x & 15, kt = x >> 4;
        const float* src; bf16 *hi, *lo;
        float sc = 1.0f;
        size_t lsrc = (size_t)layer * D_ * D_;
        if (grp == 0)      { src = Wq + lsrc; hi = wqh + (size_t)layer * QKVN * D_;            lo = wql + (size_t)layer * QKVN * D_; sc = 0.125f; }
        else if (grp == 1) { src = Wk + lsrc; hi = wqh + (size_t)layer * QKVN * D_ + D_ * D_;  lo = wql + (size_t)layer * QKVN * D_ + D_ * D_; }
        else if (grp == 2) { src = Wv + lsrc; hi = wqh + (size_t)layer * QKVN * D_ + 2*D_*D_;  lo = wql + (size_t)layer * QKVN * D_ + 2*D_*D_; }
        else               { src = Wo + lsrc; hi = woh + (size_t)layer * D_ * D_;              lo = wol + (size_t)layer * D_ * D_; }
        tsplit_tile(src, hi, lo, D_, D_, nt * 32, kt * 32, sc);
    } else if (grp == 4) {
        int nt = x & 63, kt = x >> 6;
        tsplit_tile(W1 + (size_t)layer * D_ * FF_,
                    w1h + (size_t)layer * FF_ * D_, w1l + (size_t)layer * FF_ * D_,
                    D_, FF_, nt * 32, kt * 32, 1.0f);
    } else if (grp == 5) {
        int nt = x & 15, kt = x >> 4;
        tsplit_tile(W2 + (size_t)layer * FF_ * D_,
                    w2h + (size_t)layer * D_ * FF_, w2l + (size_t)layer * D_ * FF_,
                    FF_, D_, nt * 32, kt * 32, 1.0f);
    } else {
        if (x >= 6) return;
        int idx = x * 256 + threadIdx.x;
        int n = idx;
        float v;
        if (n < D_)          v = bq[layer * D_ + n] * 0.125f;
        else if (n < 2 * D_) v = bk[layer * D_ + n - D_];
        else                 v = bv[layer * D_ + n - 2 * D_];
        bqkv[layer * QKVN + idx] = v;
    }
}

// ---------------- embedding ----------------
__global__ void embed_kernel(const int* __restrict__ tok, const float* __restrict__ gp,
                             const float* __restrict__ temb, const float* __restrict__ pemb,
                             float* __restrict__ x) {
    int idx = blockIdx.x * blockDim.x + threadIdx.x;
    int d  = idx & (D_ - 1);
    int bs = idx >> 9;
    int s  = bs % S_;
    int b  = bs / S_;
    float v;
    if (s == 0)            v = temb[(size_t)tok[b * T_] * D_ + d];
    else if (s <= NP_)     v = gp[((size_t)b * DG_) * NP_ * D_ + (s - 1) * D_ + d];
    else                   v = temb[(size_t)tok[b * T_ + (s - NP_)] * D_ + d];
    x[idx] = v + pemb[s * D_ + d];
}

// ---------------- layernorm, warp-per-row (+ fused prompt replace) ------------
__global__ void __launch_bounds__(256)
ln_split_kernel(float* __restrict__ x, const float* __restrict__ p, int bstride,
                const float* __restrict__ g, const float* __restrict__ bb,
                bf16* __restrict__ hi, bf16* __restrict__ lo) {
    int warp = threadIdx.x >> 5, lane = threadIdx.x & 31;
    int row = blockIdx.x * 8 + warp;
    if (row >= MROWS) return;
    int b = row / S_, s = row - b * S_;
    bool isp = (p != nullptr) && (s >= 1) && (s <= NP_);
    const float* srcrow = isp ? (p + (size_t)b * bstride + (size_t)(s - 1) * D_)
                              : (x + (size_t)row * D_);
    float4 v4[4];
    float su = 0.0f, ss = 0.0f;
    #pragma unroll
    for (int i = 0; i < 4; i++) {
        v4[i] = ((const float4*)srcrow)[lane + i * 32];
        su += v4[i].x + v4[i].y + v4[i].z + v4[i].w;
        ss += v4[i].x * v4[i].x + v4[i].y * v4[i].y + v4[i].z * v4[i].z + v4[i].w * v4[i].w;
    }
    if (isp) {
        #pragma unroll
        for (int i = 0; i < 4; i++)
            ((float4*)(x + (size_t)row * D_))[lane + i * 32] = v4[i];
    }
    #pragma unroll
    for (int o = 16; o > 0; o >>= 1) {
        su += __shfl_xor_sync(0xffffffffu, su, o);
        ss += __shfl_xor_sync(0xffffffffu, ss, o);
    }
    float mean = su * (1.0f / D_);
    float var  = ss * (1.0f / D_) - mean * mean;
    float rstd = rsqrtf(var + 1e-5f);
    #pragma unroll
    for (int i = 0; i < 4; i++) {
        float4 gv = ((const float4*)g)[lane + i * 32];
        float4 bv = ((const float4*)bb)[lane + i * 32];
        float o0 = (v4[i].x - mean) * rstd * gv.x + bv.x;
        float o1 = (v4[i].y - mean) * rstd * gv.y + bv.y;
        float o2 = (v4[i].z - mean) * rstd * gv.z + bv.z;
        float o3 = (v4[i].w - mean) * rstd * gv.w + bv.w;
        size_t o = (size_t)row * D_ + (lane + i * 32) * 4;
        __nv_bfloat162 h01 = __floats2bfloat162_rn(o0, o1);
        __nv_bfloat162 h23 = __floats2bfloat162_rn(o2, o3);
        *(__nv_bfloat162*)(hi + o)     = h01;
        *(__nv_bfloat162*)(hi + o + 2) = h23;
        float l0 = o0 - __low2float(h01);
        float l1 = o1 - __high2float(h01);
        float l2 = o2 - __low2float(h23);
        float l3 = o3 - __high2float(h23);
        *(__nv_bfloat162*)(lo + o)     = __floats2bfloat162_rn(l0, l1);
        *(__nv_bfloat162*)(lo + o + 2) = __floats2bfloat162_rn(l2, l3);
    }
}

// ---------------- shared epilogue ----------------
template<int MODE>
__device__ __forceinline__ void epi_write(float v0, float v1, size_t off, int c,
                                          const float* bias, const float* res,
                                          float* Cf, bf16* Chi, bf16* Clo) {
    v0 += bias[c]; v1 += bias[c + 1];
    if (MODE == 0) {
        *(float2*)(Cf + off) = make_float2(v0, v1);   // q-scale folded into weights
    } else if (MODE == 1) {
        float2 rr = *(const float2*)(res + off);
        *(float2*)(Cf + off) = make_float2(v0 + rr.x, v1 + rr.y);
    } else {
        v0 = v0 / (1.0f + __expf(-1.702f * v0));
        v1 = v1 / (1.0f + __expf(-1.702f * v1));
        __nv_bfloat162 h = __floats2bfloat162_rn(v0, v1);
        *(__nv_bfloat162*)(Chi + off) = h;
        float l0 = v0 - __low2float(h);
        float l1 = v1 - __high2float(h);
        *(__nv_bfloat162*)(Clo + off) = __floats2bfloat162_rn(l0, l1);
    }
}

// term-major MMA issue (round-6 exact), parameterized M-fragment count
#define MMA_TERMMAJOR(MF)                                                  \
    _Pragma("unroll")                                                      \
    for (int term = 0; term < 3; term++) {                                 \
        _Pragma("unroll")                                                  \
        for (int mf = 0; mf < MF; mf++) {                                  \
            _Pragma("unroll")                                              \
            for (int nf = 0; nf < 4; nf++) {                               \
                const uint32_t* a = (term == 2) ? aL[mf] : aH[mf];         \
                const uint32_t* b = (term == 1) ? &bL[nf >> 1][(nf & 1) * 2] \
                                                : &bH[nf >> 1][(nf & 1) * 2]; \
                mma16816(acc[mf][nf], a, b);                               \
            }                                                              \
        }                                                                  \
    }

// ---------------- GEMM A: 128x128 tile, 512 thr, 32x32 warp tiles, 3-stage ----
// (round-10 / round-6 best measured configuration, byte-for-byte)
constexpr int STAGE_A = 65536;
constexpr int SMEM_A_TOT = 3 * STAGE_A;     // 192KB

template<int MODE>
__global__ void __launch_bounds__(512)
gemm_mma128(const bf16* __restrict__ Ahi, const bf16* __restrict__ Alo,
            const bf16* __restrict__ Bhi, const bf16* __restrict__ Blo,
            const float* __restrict__ bias, const float* __restrict__ res,
            float* __restrict__ Cf, bf16* __restrict__ Chi, bf16* __restrict__ Clo,
            int N, int K) {
    extern __shared__ __align__(128) char smraw[];
    uint32_t sb = smem_u32(smraw);

    int tid = threadIdx.x, wid = tid >> 5, lane = tid & 31;
    int wm = wid >> 2, wn = wid & 3;
    int m0 = blockIdx.y * 128, n0 = blockIdx.x * 128;

    float acc[2][4][4];
    #pragma unroll
    for (int i = 0; i < 2; i++)
        #pragma unroll
        for (int j = 0; j < 4; j++)
            #pragma unroll
            for (int r = 0; r < 4; r++) acc[i][j][r] = 0.0f;

    const int nk = K >> 6;

    auto load_stage = [&](int buf, int kt2) {
        int k0 = kt2 << 6;
        uint32_t sb0 = sb + buf * STAGE_A;
        #pragma unroll
        for (int t = 0; t < 2; t++) {
            int idx = tid + t * 512;
            int row = idx >> 3, u = idx & 7;
            uint32_t so = sb0 + (row << 7) + ((u ^ (row & 7)) << 4);
            size_t ea = (size_t)(m0 + row) * K + k0 + u * 8;
            CP16(so,         Ahi + ea);
            CP16(so + 16384, Alo + ea);
        }
        #pragma unroll
        for (int t = 0; t < 2; t++) {
            int idx = tid + t * 512;
            int row = idx >> 3, u = idx & 7;
            uint32_t so = sb0 + 32768 + (row << 7) + ((u ^ (row & 7)) << 4);
            size_t eb = (size_t)(n0 + row) * K + k0 + u * 8;
            CP16(so,         Bhi + eb);
            CP16(so + 16384, Blo + eb);
        }
    };

    load_stage(0, 0); CP_COMMIT();
    load_stage(1, 1); CP_COMMIT();

    int lr = lane & 15, lu = lane >> 4;
    int bnn = wn * 32 + ((lane >> 4) << 3) + (lane & 7);
    int bus = (lane >> 3) & 1;

    for (int kt = 0; kt < nk; kt++) {
        if (kt < nk - 1) CP_WAIT1(); else CP_WAIT0();
        __syncthreads();
        if (kt + 2 < nk) { load_stage((kt + 2) % 3, kt + 2); CP_COMMIT(); }

        uint32_t base = sb + (kt % 3) * STAGE_A;
        #pragma unroll
        for (int kk = 0; kk < 4; kk++) {
            uint32_t aH[2][4], aL[2][4], bH[2][4], bL[2][4];
            #pragma unroll
            for (int mf = 0; mf < 2; mf++) {
                int r = wm * 32 + mf * 16 + lr;
                int u = kk * 2 + lu;
                uint32_t ad = base + (r << 7) + ((u ^ (r & 7)) << 4);
                ldsm4(aH[mf], ad);
                ldsm4(aL[mf], ad + 16384);
            }
            #pragma unroll
            for (int j = 0; j < 2; j++) {
                int n = bnn + j * 16;
                int u = kk * 2 + bus;
                uint32_t bd = base + 32768 + (n << 7) + ((u ^ (n & 7)) << 4);
                ldsm4(bH[j], bd);
                ldsm4(bL[j], bd + 16384);
            }
            MMA_TERMMAJOR(2);
        }
    }

    int r0b = m0 + wm * 32 + (lane >> 2);
    int cb  = n0 + wn * 32 + 2 * (lane & 3);
    #pragma unroll
    for (int mf = 0; mf < 2; mf++)
        #pragma unroll
        for (int nf = 0; nf < 4; nf++) {
            int c = cb + nf * 8;
            #pragma unroll
            for (int half = 0; half < 2; half++) {
                int r = r0b + mf * 16 + half * 8;
                size_t off = (size_t)r * N + c;
                epi_write<MODE>(acc[mf][nf][half * 2], acc[mf][nf][half * 2 + 1],
                                off, c, bias, res, Cf, Chi, Clo);
            }
        }
}

// ---------------- GEMM B: 128x64 tile, 256 threads, 2-stage, 2 CTAs/SM -------
// (round-6 best measured configuration, byte-for-byte)
constexpr int STAGE_B = 49152;
constexpr int SMEM_B_TOT = 2 * STAGE_B;     // 96KB -> 2 CTAs/SM

template<int MODE>
__global__ void __launch_bounds__(256, 2)
gemm_mma64(const bf16* __restrict__ Ahi, const bf16* __restrict__ Alo,
           const bf16* __restrict__ Bhi, const bf16* __restrict__ Blo,
           const float* __restrict__ bias, const float* __restrict__ res,
           float* __restrict__ Cf, bf16* __restrict__ Chi, bf16* __restrict__ Clo,
           int N, int K) {
    extern __shared__ __align__(128) char smraw[];
    uint32_t sb = smem_u32(smraw);

    int tid = threadIdx.x, wid = tid >> 5, lane = tid & 31;
    int wm = wid >> 1, wn = wid & 1;
    int m0 = blockIdx.y * 128, n0 = blockIdx.x * 64;

    float acc[2][4][4];
    #pragma unroll
    for (int i = 0; i < 2; i++)
        #pragma unroll
        for (int j = 0; j < 4; j++)
            #pragma unroll
            for (int r = 0; r < 4; r++) acc[i][j][r] = 0.0f;

    const int nk = K >> 6;

    auto load_stage = [&](int buf, int kt2) {
        int k0 = kt2 << 6;
        uint32_t sb0 = sb + buf * STAGE_B;
        #pragma unroll
        for (int t = 0; t < 4; t++) {
            int idx = tid + t * 256;
            int row = idx >> 3, u = idx & 7;
            uint32_t so = sb0 + (row << 7) + ((u ^ (row & 7)) << 4);
            size_t ea = (size_t)(m0 + row) * K + k0 + u * 8;
            CP16(so,         Ahi + ea);
            CP16(so + 16384, Alo + ea);
        }
        #pragma unroll
        for (int t = 0; t < 2; t++) {
            int idx = tid + t * 256;
            int row = idx >> 3, u = idx & 7;
            uint32_t so = sb0 + 32768 + (row << 7) + ((u ^ (row & 7)) << 4);
            size_t eb = (size_t)(n0 + row) * K + k0 + u * 8;
            CP16(so,        Bhi + eb);
            CP16(so + 8192, Blo + eb);
        }
    };

    load_stage(0, 0); CP_COMMIT();

    int lr = lane & 15, lu = lane >> 4;
    int bnn = wn * 32 + ((lane >> 4) << 3) + (lane & 7);
    int bus = (lane >> 3) & 1;

    for (int kt = 0; kt < nk; kt++) {
        CP_WAIT0();
        __syncthreads();
        if (kt + 1 < nk) { load_stage((kt + 1) & 1, kt + 1); CP_COMMIT(); }

        uint32_t base = sb + (kt & 1) * STAGE_B;
        #pragma unroll
        for (int kk = 0; kk < 4; kk++) {
            uint32_t aH[2][4], aL[2][4], bH[2][4], bL[2][4];
            #pragma unroll
            for (int mf = 0; mf < 2; mf++) {
                int r = wm * 32 + mf * 16 + lr;
                int u = kk * 2 + lu;
                uint32_t ad = base + (r << 7) + ((u ^ (r & 7)) << 4);
                ldsm4(aH[mf], ad);
                ldsm4(aL[mf], ad + 16384);
            }
            #pragma unroll
            for (int j = 0; j < 2; j++) {
                int n = bnn + j * 16;
                int u = kk * 2 + bus;
                uint32_t bd = base + 32768 + (n << 7) + ((u ^ (n & 7)) << 4);
                ldsm4(bH[j], bd);
                ldsm4(bL[j], bd + 8192);
            }
            MMA_TERMMAJOR(2);
        }
        __syncthreads();
    }

    int r0b = m0 + wm * 32 + (lane >> 2);
    int cb  = n0 + wn * 32 + 2 * (lane & 3);
    #pragma unroll
    for (int mf = 0; mf < 2; mf++)
        #pragma unroll
        for (int nf = 0; nf < 4; nf++) {
            int c = cb + nf * 8;
            #pragma unroll
            for (int half = 0; half < 2; half++) {
                int r = r0b + mf * 16 + half * 8;
                size_t off = (size_t)r * N + c;
                epi_write<MODE>(acc[mf][nf][half * 2], acc[mf][nf][half * 2 + 1],
                                off, c, bias, res, Cf, Chi, Clo);
            }
        }
}

// ---------------- fused attention: one block per (b, h), 2 queries/warp pass --
// sK/sV reads shared across the query pair -> ~half the SMEM crossbar bytes.
// Per-query arithmetic order identical to the single-query version.
__global__ void __launch_bounds__(256)
attn_kernel(const float* __restrict__ qkv, const int* __restrict__ amask,
            bf16* __restrict__ ohi, bf16* __restrict__ olo) {
    __shared__ float sK[S_][DH_ + 1];
    __shared__ float sV[S_][DH_];          // unpadded: j uniform per access -> conflict-free
    __shared__ float sQ[8][2][DH_];
    __shared__ float sP[8][2][S_ + 1];
    __shared__ int   sM[S_];
    int h = blockIdx.x, b = blockIdx.y;
    int tid = threadIdx.x, lane = tid & 31, w = tid >> 5;

    for (int i = tid; i < S_ * DH_; i += 256) {
        int s = i >> 6, d = i & 63;
        size_t base = ((size_t)(b * S_ + s)) * QKVN + h * DH_ + d;
        sK[s][d] = qkv[base + D_];
        sV[s][d] = qkv[base + 2 * D_];
    }
    for (int i = tid; i < S_; i += 256)
        sM[i] = (i < NP_) ? 1 : amask[b * T_ + i - NP_];
    __syncthreads();

    #pragma unroll
    for (int t = 0; t < 5; t++) {
        int qa = w + 16 * t;               // qa <= 7 + 64 = 71 < 77 always
        int qb = qa + 8;
        bool hasb = (qb < S_);
        int qbl = hasb ? qb : qa;          // clamp to keep global reads in-bounds
        size_t qoffa = ((size_t)(b * S_ + qa))  * QKVN + h * DH_;
        size_t qoffb = ((size_t)(b * S_ + qbl)) * QKVN + h * DH_;
        sQ[w][0][lane]      = qkv[qoffa + lane];
        sQ[w][0][lane + 32] = qkv[qoffa + lane + 32];
        sQ[w][1][lane]      = qkv[qoffb + lane];
        sQ[w][1][lane + 32] = qkv[qoffb + lane + 32];
        __syncwarp();
        int nja = qa + 1;
        int njb = hasb ? (qb + 1) : nja;

        float sca[3], scb[3];
        #pragma unroll
        for (int tt = 0; tt < 3; tt++) {
            int j = lane + 32 * tt;
            float da = -3.0e38f, db = -3.0e38f;
            if (j < njb) {
                float sa = 0.0f, sb2 = 0.0f;
                #pragma unroll
                for (int dd = 0; dd < DH_; dd++) {
                    float kj = sK[j][dd];
                    sa  += sQ[w][0][dd] * kj;
                    sb2 += sQ[w][1][dd] * kj;
                }
                if (sM[j] == 0) { sa = -1.0e30f; sb2 = -1.0e30f; }
                if (j < nja) da = sa;
                db = sb2;
            }
            sca[tt] = da;
            scb[tt] = db;
        }

        // softmax qa
        {
            float m = fmaxf(sca[0], fmaxf(sca[1], sca[2]));
            #pragma unroll
            for (int o2 = 16; o2 > 0; o2 >>= 1) m = fmaxf(m, __shfl_xor_sync(0xffffffffu, m, o2));
            float e[3], esum = 0.0f;
            #pragma unroll
            for (int tt = 0; tt < 3; tt++) {
                int j = lane + 32 * tt;
                e[tt] = (j < nja) ? __expf(sca[tt] - m) : 0.0f;
                esum += e[tt];
            }
            #pragma unroll
            for (int o2 = 16; o2 > 0; o2 >>= 1) esum += __shfl_xor_sync(0xffffffffu, esum, o2);
            float inv = 1.0f / esum;
            #pragma unroll
            for (int tt = 0; tt < 3; tt++) {
                int j = lane + 32 * tt;
                if (j < nja) sP[w][0][j] = e[tt] * inv;
            }
        }
        // softmax qb
        if (hasb) {
            float m = fmaxf(scb[0], fmaxf(scb[1], scb[2]));
            #pragma unroll
            for (int o2 = 16; o2 > 0; o2 >>= 1) m = fmaxf(m, __shfl_xor_sync(0xffffffffu, m, o2));
            float e[3], esum = 0.0f;
            #pragma unroll
            for (int tt = 0; tt < 3; tt++) {
                int j = lane + 32 * tt;
                e[tt] = (j < njb) ? __expf(scb[tt] - m) : 0.0f;
                esum += e[tt];
            }
            #pragma unroll
            for (int o2 = 16; o2 > 0; o2 >>= 1) esum += __shfl_xor_sync(0xffffffffu, esum, o2);
            float inv = 1.0f / esum;
            #pragma unroll
            for (int tt = 0; tt < 3; tt++) {
                int j = lane + 32 * tt;
                if (j < njb) sP[w][1][j] = e[tt] * inv;
            }
        }
        __syncwarp();

        // PV: shared sV reads for both queries over the common range
        float aa0 = 0.0f, aa1 = 0.0f, ab0 = 0.0f, ab1 = 0.0f;
        for (int j = 0; j < nja; j++) {
            float v0 = sV[j][lane], v1 = sV[j][lane + 32];
            float pa = sP[w][0][j];
            float pb = sP[w][1][j];
            aa0 += pa * v0; aa1 += pa * v1;
            ab0 += pb * v0; ab1 += pb * v1;
        }
        for (int j = nja; j < njb; j++) {
            float v0 = sV[j][lane], v1 = sV[j][lane + 32];
            float pb = sP[w][1][j];
            ab0 += pb * v0; ab1 += pb * v1;
        }

        size_t ooffa = ((size_t)(b * S_ + qa)) * D_ + h * DH_;
        bf16 ha0 = __float2bfloat16(aa0);
        ohi[ooffa + lane] = ha0;
        olo[ooffa + lane] = __float2bfloat16(aa0 - __bfloat162float(ha0));
        bf16 ha1 = __float2bfloat16(aa1);
        ohi[ooffa + lane + 32] = ha1;
        olo[ooffa + lane + 32] = __float2bfloat16(aa1 - __bfloat162float(ha1));
        if (hasb) {
            size_t ooffb = ((size_t)(b * S_ + qb)) * D_ + h * DH_;
            bf16 hb0 = __float2bfloat16(ab0);
            ohi[ooffb + lane] = hb0;
            olo[ooffb + lane] = __float2bfloat16(ab0 - __bfloat162float(hb0));
            bf16 hb1 = __float2bfloat16(ab1);
            ohi[ooffb + lane + 32] = hb1;
            olo[ooffb + lane + 32] = __float2bfloat16(ab1 - __bfloat162float(hb1));
        }
        __syncwarp();
    }
}

// ---------------- final: argmax gather + layernorm -> out ----------------
__device__ __forceinline__ float2 block_sum2(float s, float ss) {
    __shared__ float sh1[4], sh2[4];
    int lane = threadIdx.x & 31, w = threadIdx.x >> 5;
    #pragma unroll
    for (int o = 16; o > 0; o >>= 1) {
        s  += __shfl_down_sync(0xffffffffu, s,  o);
        ss += __shfl_down_sync(0xffffffffu, ss, o);
    }
    if (lane == 0) { sh1[w] = s; sh2[w] = ss; }
    __syncthreads();
    return make_float2(sh1[0] + sh1[1] + sh1[2] + sh1[3],
                       sh2[0] + sh2[1] + sh2[2] + sh2[3]);
}

__global__ void __launch_bounds__(128)
final_kernel(const float* __restrict__ x, const int* __restrict__ tok,
             const float* __restrict__ g, const float* __restrict__ bb,
             float* __restrict__ out) {
    int b = blockIdx.x, tid = threadIdx.x;
    __shared__ int sval[128];
    __shared__ int srow;
    sval[tid] = (tid < T_) ? tok[b * T_ + tid] : (-2147483647 - 1);
    __syncthreads();
    if (tid == 0) {
        int best = sval[0], bi = 0;
        for (int t = 1; t < T_; t++)
            if (sval[t] > best) { best = sval[t]; bi = t; }
        srow = bi + NP_;
    }
    __syncthreads();
    int row = b * S_ + srow;
    float4 vv = ((const float4*)(x + (size_t)row * D_))[tid];
    float s  = vv.x + vv.y + vv.z + vv.w;
    float ss = vv.x * vv.x + vv.y * vv.y + vv.z * vv.z + vv.w * vv.w;
    float2 tot = block_sum2(s, ss);
    float mean = tot.x * (1.0f / D_);
    float var  = tot.y * (1.0f / D_) - mean * mean;
    float rstd = rsqrtf(var + 1e-5f);
    float4 gv = ((const float4*)g)[tid];
    float4 bv = ((const float4*)bb)[tid];
    float4 ov;
    ov.x = (vv.x - mean) * rstd * gv.x + bv.x;
    ov.y = (vv.y - mean) * rstd * gv.y + bv.y;
    ov.z = (vv.z - mean) * rstd * gv.z + bv.z;
    ov.w = (vv.w - mean) * rstd * gv.w + bv.w;
    ((float4*)(out + (size_t)b * D_))[tid] = ov;
}

// ---------------- launch ----------------
extern "C" void kernel_launch(void* const* d_in, const int* in_sizes, int n_in,
                              void* d_out, int out_size) {
    (void)in_sizes; (void)n_in; (void)out_size;
    const int*   tok   = (const int*)  d_in[0];
    const int*   amask = (const int*)  d_in[1];
    const float* gp    = (const float*)d_in[2];
    const float* sp    = (const float*)d_in[3];
    const float* temb  = (const float*)d_in[4];
    const float* pemb  = (const float*)d_in[5];
    const float* ln1g  = (const float*)d_in[6];
    const float* ln1b  = (const float*)d_in[7];
    const float* Wq    = (const float*)d_in[8];
    const float* bq    = (const float*)d_in[9];
    const float* Wk    = (const float*)d_in[10];
    const float* bk    = (const float*)d_in[11];
    const float* Wv    = (const float*)d_in[12];
    const float* bv    = (const float*)d_in[13];
    const float* Wo    = (const float*)d_in[14];
    const float* bo    = (const float*)d_in[15];
    const float* ln2g  = (const float*)d_in[16];
    const float* ln2b  = (const float*)d_in[17];
    const float* W1    = (const float*)d_in[18];
    const float* b1    = (const float*)d_in[19];
    const float* W2    = (const float*)d_in[20];
    const float* b2    = (const float*)d_in[21];
    const float* lnfg  = (const float*)d_in[22];
    const float* lnfb  = (const float*)d_in[23];
    float* out = (float*)d_out;

    float *x, *qkv, *bqkv;
    bf16 *hhi, *hlo, *ohi, *olo, *fhi, *flo;
    bf16 *wqh, *wql, *woh, *wol, *w1h, *w1l, *w2h, *w2l;
    cudaGetSymbolAddress((void**)&x,   g_x);
    cudaGetSymbolAddress((void**)&hhi, g_hhi);
    cudaGetSymbolAddress((void**)&hlo, g_hlo);
    cudaGetSymbolAddress((void**)&qkv, g_qkv);
    cudaGetSymbolAddress((void**)&ohi, g_ohi);
    cudaGetSymbolAddress((void**)&olo, g_olo);
    cudaGetSymbolAddress((void**)&fhi, g_fhi);
    cudaGetSymbolAddress((void**)&flo, g_flo);
    cudaGetSymbolAddress((void**)&wqh, w_qkv_hi);
    cudaGetSymbolAddress((void**)&wql, w_qkv_lo);
    cudaGetSymbolAddress((void**)&woh, w_o_hi);
    cudaGetSymbolAddress((void**)&wol, w_o_lo);
    cudaGetSymbolAddress((void**)&w1h, w_1_hi);
    cudaGetSymbolAddress((void**)&w1l, w_1_lo);
    cudaGetSymbolAddress((void**)&w2h, w_2_hi);
    cudaGetSymbolAddress((void**)&w2l, w_2_lo);
    cudaGetSymbolAddress((void**)&bqkv, g_bqkv);

    cudaFuncSetAttribute(gemm_mma128<0>, cudaFuncAttributeMaxDynamicSharedMemorySize, SMEM_A_TOT);
    cudaFuncSetAttribute(gemm_mma128<2>, cudaFuncAttributeMaxDynamicSharedMemorySize, SMEM_A_TOT);
    cudaFuncSetAttribute(gemm_mma64<1>,  cudaFuncAttributeMaxDynamicSharedMemorySize, SMEM_B_TOT);

    prep_kernel<<<dim3(1024, 7, NL_), 256>>>(Wq, Wk, Wv, Wo, W1, W2, bq, bk, bv,
                                             wqh, wql, woh, wol, w1h, w1l, w2h, w2l, bqkv);
    embed_kernel<<<(B_ * S_ * D_) / 256, 256>>>(tok, gp, temb, pemb, x);

    dim3 gQKV(QKVN / 128, MROWS / 128);   // (12, 77)
    dim3 gFF (FF_  / 128, MROWS / 128);   // (16, 77)
    dim3 gD64(D_   / 64,  MROWS / 128);   // (8, 77) = 616 CTAs
    int lnGrid = MROWS / 8;               // 1232

    for (int i = 0; i < NL_; i++) {
        const float* p = nullptr; int bs = 0;
        if (i > 0) {
            if (i < DG_) { p = gp + (size_t)i * NP_ * D_;                 bs = DG_ * NP_ * D_; }
            else         { p = sp + (size_t)(i - (NL_ - DS_)) * NP_ * D_; bs = DS_ * NP_ * D_; }
        }
        ln_split_kernel<<<lnGrid, 256>>>(x, p, bs, ln1g + i * D_, ln1b + i * D_, hhi, hlo);
        gemm_mma128<0><<<gQKV, 512, SMEM_A_TOT>>>(hhi, hlo,
            wqh + (size_t)i * QKVN * D_, wql + (size_t)i * QKVN * D_,
            bqkv + i * QKVN, nullptr, qkv, nullptr, nullptr, QKVN, D_);
        attn_kernel<<<dim3(H_, B_), 256>>>(qkv, amask, ohi, olo);
        gemm_mma64<1><<<gD64, 256, SMEM_B_TOT>>>(ohi, olo,
            woh + (size_t)i * D_ * D_, wol + (size_t)i * D_ * D_,
            bo + i * D_, x, x, nullptr, nullptr, D_, D_);
        ln_split_kernel<<<lnGrid, 256>>>(x, nullptr, 0, ln2g + i * D_, ln2b + i * D_, hhi, hlo);
        gemm_mma128<2><<<gFF, 512, SMEM_A_TOT>>>(hhi, hlo,
            w1h + (size_t)i * FF_ * D_, w1l + (size_t)i * FF_ * D_,
            b1 + i * FF_, nullptr, nullptr, fhi, flo, FF_, D_);
        gemm_mma64<1><<<gD64, 256, SMEM_B_TOT>>>(fhi, flo,
            w2h + (size_t)i * D_ * FF_, w2l + (size_t)i * D_ * FF_,
            b2 + i * D_, x, x, nullptr, nullptr, D_, FF_);
    }
    final_kernel<<<B_, 128>>>(x, tok, lnfg, lnfb, out);
}

// round 14
// speedup vs baseline: 1.0744x; 1.0744x over previous
#include <cuda_runtime.h>
#include <cuda_bf16.h>
#include <math.h>
#include <stdint.h>

typedef __nv_bfloat16 bf16;

// ---------------- problem constants ----------------
constexpr int B_  = 128;
constexpr int T_  = 69;
constexpr int S_  = 77;
constexpr int D_  = 512;
constexpr int H_  = 8;
constexpr int DH_ = 64;
constexpr int NL_ = 12;
constexpr int FF_ = 2048;
constexpr int NP_ = 8;
constexpr int DG_ = 6;
constexpr int DS_ = 6;
constexpr int MROWS = B_ * S_;   // 9856 = 77 * 128
constexpr int QKVN  = 3 * D_;    // 1536

// ---------------- scratch (device globals; no runtime alloc) ----------------
__device__ __align__(128) float g_x  [MROWS * D_];
__device__ __align__(128) bf16  g_hhi[MROWS * D_];
__device__ __align__(128) bf16  g_hlo[MROWS * D_];
__device__ __align__(128) float g_qkv[MROWS * QKVN];
__device__ __align__(128) bf16  g_ohi[MROWS * D_];
__device__ __align__(128) bf16  g_olo[MROWS * D_];
__device__ __align__(128) bf16  g_fhi[MROWS * FF_];
__device__ __align__(128) bf16  g_flo[MROWS * FF_];

// transposed weight splits [layer][N][K] (K-major)
__device__ __align__(128) bf16  w_qkv_hi[NL_ * QKVN * D_];
__device__ __align__(128) bf16  w_qkv_lo[NL_ * QKVN * D_];
__device__ __align__(128) bf16  w_o_hi  [NL_ * D_ * D_];
__device__ __align__(128) bf16  w_o_lo  [NL_ * D_ * D_];
__device__ __align__(128) bf16  w_1_hi  [NL_ * FF_ * D_];
__device__ __align__(128) bf16  w_1_lo  [NL_ * FF_ * D_];
__device__ __align__(128) bf16  w_2_hi  [NL_ * D_ * FF_];
__device__ __align__(128) bf16  w_2_lo  [NL_ * D_ * FF_];
__device__ float g_bqkv  [NL_ * QKVN];

// ---------------- PTX helpers ----------------
__device__ __forceinline__ uint32_t smem_u32(const void* p) {
    uint32_t a;
    asm("{ .reg .u64 t; cvta.to.shared.u64 t, %1; cvt.u32.u64 %0, t; }" : "=r"(a) : "l"(p));
    return a;
}

#define CP16(saddr, gptr) \
    asm volatile("cp.async.cg.shared.global [%0], [%1], 16;" :: "r"(saddr), "l"(gptr) : "memory")
#define CP_COMMIT() asm volatile("cp.async.commit_group;" ::: "memory")
#define CP_WAIT1()  asm volatile("cp.async.wait_group 1;" ::: "memory")
#define CP_WAIT0()  asm volatile("cp.async.wait_group 0;" ::: "memory")

__device__ __forceinline__ void ldsm4(uint32_t* r, uint32_t addr) {
    asm volatile("ldmatrix.sync.aligned.m8n8.x4.shared.b16 {%0,%1,%2,%3}, [%4];"
                 : "=r"(r[0]), "=r"(r[1]), "=r"(r[2]), "=r"(r[3]) : "r"(addr));
}

__device__ __forceinline__ void mma16816(float* d, const uint32_t* a, const uint32_t* b) {
    asm volatile(
        "mma.sync.aligned.m16n8k16.row.col.f32.bf16.bf16.f32 "
        "{%0,%1,%2,%3}, {%4,%5,%6,%7}, {%8,%9}, {%0,%1,%2,%3};"
        : "+f"(d[0]), "+f"(d[1]), "+f"(d[2]), "+f"(d[3])
        : "r"(a[0]), "r"(a[1]), "r"(a[2]), "r"(a[3]), "r"(b[0]), "r"(b[1]));
}

// ---------------- unified preprocessing (1 launch) ----------------
__device__ __forceinline__ void tsplit_tile(const float* src, bf16* hi, bf16* lo,
                                            int K, int N, int n0, int k0, float scale) {
    __shared__ float t[32][33];
    int lx = threadIdx.x & 31, ly = threadIdx.x >> 5;
    #pragma unroll
    for (int i = ly; i < 32; i += 8)
        t[i][lx] = src[(size_t)(k0 + i) * N + n0 + lx];
    __syncthreads();
    #pragma unroll
    for (int i = ly; i < 32; i += 8) {
        float v = t[lx][i] * scale;
        size_t o = (size_t)(n0 + i) * K + k0 + lx;
        bf16 h = __float2bfloat16(v);
        hi[o] = h;
        lo[o] = __float2bfloat16(v - __bfloat162float(h));
    }
}

__global__ void __launch_bounds__(256)
prep_kernel(const float* __restrict__ Wq, const float* __restrict__ Wk,
            const float* __restrict__ Wv, const float* __restrict__ Wo,
            const float* __restrict__ W1, const float* __restrict__ W2,
            const float* __restrict__ bq, const float* __restrict__ bk,
            const float* __restrict__ bv,
            bf16* __restrict__ wqh, bf16* __restrict__ wql,
            bf16* __restrict__ woh, bf16* __restrict__ wol,
            bf16* __restrict__ w1h, bf16* __restrict__ w1l,
            bf16* __restrict__ w2h, bf16* __restrict__ w2l,
            float* __restrict__ bqkv) {
    int grp = blockIdx.y, layer = blockIdx.z, x = blockIdx.x;
    if (grp < 4) {
        if (x >= 256) return;
        int nt = x & 15, kt = x >> 4;
        const float* src; bf16 *hi, *lo;
        float sc = 1.0f;
        size_t lsrc = (size_t)layer * D_ * D_;
        if (grp == 0)      { src = Wq + lsrc; hi = wqh + (size_t)layer * QKVN * D_;            lo = wql + (size_t)layer * QKVN * D_; sc = 0.125f; }
        else if (grp == 1) { src = Wk + lsrc; hi = wqh + (size_t)layer * QKVN * D_ + D_ * D_;  lo = wql + (size_t)layer * QKVN * D_ + D_ * D_; }
        else if (grp == 2) { src = Wv + lsrc; hi = wqh + (size_t)layer * QKVN * D_ + 2*D_*D_;  lo = wql + (size_t)layer * QKVN * D_ + 2*D_*D_; }
        else               { src = Wo + lsrc; hi = woh + (size_t)layer * D_ * D_;              lo = wol + (size_t)layer * D_ * D_; }
        tsplit_tile(src, hi, lo, D_, D_, nt * 32, kt * 32, sc);
    } else if (grp == 4) {
        int nt = x & 63, kt = x >> 6;
        tsplit_tile(W1 + (size_t)layer * D_ * FF_,
                    w1h + (size_t)layer * FF_ * D_, w1l + (size_t)layer * FF_ * D_,
                    D_, FF_, nt * 32, kt * 32, 1.0f);
    } else if (grp == 5) {
        int nt = x & 15, kt = x >> 4;
        tsplit_tile(W2 + (size_t)layer * FF_ * D_,
                    w2h + (size_t)layer * D_ * FF_, w2l + (size_t)layer * D_ * FF_,
                    FF_, D_, nt * 32, kt * 32, 1.0f);
    } else {
        if (x >= 6) return;
        int idx = x * 256 + threadIdx.x;
        int n = idx;
        float v;
        if (n < D_)          v = bq[layer * D_ + n] * 0.125f;
        else if (n < 2 * D_) v = bk[layer * D_ + n - D_];
        else                 v = bv[layer * D_ + n - 2 * D_];
        bqkv[layer * QKVN + idx] = v;
    }
}

// ---------------- embedding ----------------
__global__ void embed_kernel(const int* __restrict__ tok, const float* __restrict__ gp,
                             const float* __restrict__ temb, const float* __restrict__ pemb,
                             float* __restrict__ x) {
    int idx = blockIdx.x * blockDim.x + threadIdx.x;
    int d  = idx & (D_ - 1);
    int bs = idx >> 9;
    int s  = bs % S_;
    int b  = bs / S_;
    float v;
    if (s == 0)            v = temb[(size_t)tok[b * T_] * D_ + d];
    else if (s <= NP_)     v = gp[((size_t)b * DG_) * NP_ * D_ + (s - 1) * D_ + d];
    else                   v = temb[(size_t)tok[b * T_ + (s - NP_)] * D_ + d];
    x[idx] = v + pemb[s * D_ + d];
}

// ---------------- layernorm, warp-per-row (+ fused prompt replace) ------------
__global__ void __launch_bounds__(256)
ln_split_kernel(float* __restrict__ x, const float* __restrict__ p, int bstride,
                const float* __restrict__ g, const float* __restrict__ bb,
                bf16* __restrict__ hi, bf16* __restrict__ lo) {
    int warp = threadIdx.x >> 5, lane = threadIdx.x & 31;
    int row = blockIdx.x * 8 + warp;
    if (row >= MROWS) return;
    int b = row / S_, s = row - b * S_;
    bool isp = (p != nullptr) && (s >= 1) && (s <= NP_);
    const float* srcrow = isp ? (p + (size_t)b * bstride + (size_t)(s - 1) * D_)
                              : (x + (size_t)row * D_);
    float4 v4[4];
    float su = 0.0f, ss = 0.0f;
    #pragma unroll
    for (int i = 0; i < 4; i++) {
        v4[i] = ((const float4*)srcrow)[lane + i * 32];
        su += v4[i].x + v4[i].y + v4[i].z + v4[i].w;
        ss += v4[i].x * v4[i].x + v4[i].y * v4[i].y + v4[i].z * v4[i].z + v4[i].w * v4[i].w;
    }
    if (isp) {
        #pragma unroll
        for (int i = 0; i < 4; i++)
            ((float4*)(x + (size_t)row * D_))[lane + i * 32] = v4[i];
    }
    #pragma unroll
    for (int o = 16; o > 0; o >>= 1) {
        su += __shfl_xor_sync(0xffffffffu, su, o);
        ss += __shfl_xor_sync(0xffffffffu, ss, o);
    }
    float mean = su * (1.0f / D_);
    float var  = ss * (1.0f / D_) - mean * mean;
    float rstd = rsqrtf(var + 1e-5f);
    #pragma unroll
    for (int i = 0; i < 4; i++) {
        float4 gv = ((const float4*)g)[lane + i * 32];
        float4 bv = ((const float4*)bb)[lane + i * 32];
        float o0 = (v4[i].x - mean) * rstd * gv.x + bv.x;
        float o1 = (v4[i].y - mean) * rstd * gv.y + bv.y;
        float o2 = (v4[i].z - mean) * rstd * gv.z + bv.z;
        float o3 = (v4[i].w - mean) * rstd * gv.w + bv.w;
        size_t o = (size_t)row * D_ + (lane + i * 32) * 4;
        __nv_bfloat162 h01 = __floats2bfloat162_rn(o0, o1);
        __nv_bfloat162 h23 = __floats2bfloat162_rn(o2, o3);
        *(__nv_bfloat162*)(hi + o)     = h01;
        *(__nv_bfloat162*)(hi + o + 2) = h23;
        float l0 = o0 - __low2float(h01);
        float l1 = o1 - __high2float(h01);
        float l2 = o2 - __low2float(h23);
        float l3 = o3 - __high2float(h23);
        *(__nv_bfloat162*)(lo + o)     = __floats2bfloat162_rn(l0, l1);
        *(__nv_bfloat162*)(lo + o + 2) = __floats2bfloat162_rn(l2, l3);
    }
}

// ---------------- shared epilogue ----------------
template<int MODE>
__device__ __forceinline__ void epi_write(float v0, float v1, size_t off, int c,
                                          const float* bias, const float* res,
                                          float* Cf, bf16* Chi, bf16* Clo) {
    v0 += bias[c]; v1 += bias[c + 1];
    if (MODE == 0) {
        *(float2*)(Cf + off) = make_float2(v0, v1);   // q-scale folded into weights
    } else if (MODE == 1) {
        float2 rr = *(const float2*)(res + off);
        *(float2*)(Cf + off) = make_float2(v0 + rr.x, v1 + rr.y);
    } else {
        v0 = v0 / (1.0f + __expf(-1.702f * v0));
        v1 = v1 / (1.0f + __expf(-1.702f * v1));
        __nv_bfloat162 h = __floats2bfloat162_rn(v0, v1);
        *(__nv_bfloat162*)(Chi + off) = h;
        float l0 = v0 - __low2float(h);
        float l1 = v1 - __high2float(h);
        *(__nv_bfloat162*)(Clo + off) = __floats2bfloat162_rn(l0, l1);
    }
}

// term-major MMA issue (round-6 exact), parameterized M-fragment count
#define MMA_TERMMAJOR(MF)                                                  \
    _Pragma("unroll")                                                      \
    for (int term = 0; term < 3; term++) {                                 \
        _Pragma("unroll")                                                  \
        for (int mf = 0; mf < MF; mf++) {                                  \
            _Pragma("unroll")                                              \
            for (int nf = 0; nf < 4; nf++) {                               \
                const uint32_t* a = (term == 2) ? aL[mf] : aH[mf];         \
                const uint32_t* b = (term == 1) ? &bL[nf >> 1][(nf & 1) * 2] \
                                                : &bH[nf >> 1][(nf & 1) * 2]; \
                mma16816(acc[mf][nf], a, b);                               \
            }                                                              \
        }                                                                  \
    }

// ---------------- GEMM A: 128x128 tile, 512 thr, 32x32 warp tiles, 3-stage ----
// (round-10 / round-6 best measured configuration, byte-for-byte)
constexpr int STAGE_A = 65536;
constexpr int SMEM_A_TOT = 3 * STAGE_A;     // 192KB

template<int MODE>
__global__ void __launch_bounds__(512)
gemm_mma128(const bf16* __restrict__ Ahi, const bf16* __restrict__ Alo,
            const bf16* __restrict__ Bhi, const bf16* __restrict__ Blo,
            const float* __restrict__ bias, const float* __restrict__ res,
            float* __restrict__ Cf, bf16* __restrict__ Chi, bf16* __restrict__ Clo,
            int N, int K) {
    extern __shared__ __align__(128) char smraw[];
    uint32_t sb = smem_u32(smraw);

    int tid = threadIdx.x, wid = tid >> 5, lane = tid & 31;
    int wm = wid >> 2, wn = wid & 3;
    int m0 = blockIdx.y * 128, n0 = blockIdx.x * 128;

    float acc[2][4][4];
    #pragma unroll
    for (int i = 0; i < 2; i++)
        #pragma unroll
        for (int j = 0; j < 4; j++)
            #pragma unroll
            for (int r = 0; r < 4; r++) acc[i][j][r] = 0.0f;

    const int nk = K >> 6;

    auto load_stage = [&](int buf, int kt2) {
        int k0 = kt2 << 6;
        uint32_t sb0 = sb + buf * STAGE_A;
        #pragma unroll
        for (int t = 0; t < 2; t++) {
            int idx = tid + t * 512;
            int row = idx >> 3, u = idx & 7;
            uint32_t so = sb0 + (row << 7) + ((u ^ (row & 7)) << 4);
            size_t ea = (size_t)(m0 + row) * K + k0 + u * 8;
            CP16(so,         Ahi + ea);
            CP16(so + 16384, Alo + ea);
        }
        #pragma unroll
        for (int t = 0; t < 2; t++) {
            int idx = tid + t * 512;
            int row = idx >> 3, u = idx & 7;
            uint32_t so = sb0 + 32768 + (row << 7) + ((u ^ (row & 7)) << 4);
            size_t eb = (size_t)(n0 + row) * K + k0 + u * 8;
            CP16(so,         Bhi + eb);
            CP16(so + 16384, Blo + eb);
        }
    };

    load_stage(0, 0); CP_COMMIT();
    load_stage(1, 1); CP_COMMIT();

    int lr = lane & 15, lu = lane >> 4;
    int bnn = wn * 32 + ((lane >> 4) << 3) + (lane & 7);
    int bus = (lane >> 3) & 1;

    for (int kt = 0; kt < nk; kt++) {
        if (kt < nk - 1) CP_WAIT1(); else CP_WAIT0();
        __syncthreads();
        if (kt + 2 < nk) { load_stage((kt + 2) % 3, kt + 2); CP_COMMIT(); }

        uint32_t base = sb + (kt % 3) * STAGE_A;
        #pragma unroll
        for (int kk = 0; kk < 4; kk++) {
            uint32_t aH[2][4], aL[2][4], bH[2][4], bL[2][4];
            #pragma unroll
            for (int mf = 0; mf < 2; mf++) {
                int r = wm * 32 + mf * 16 + lr;
                int u = kk * 2 + lu;
                uint32_t ad = base + (r << 7) + ((u ^ (r & 7)) << 4);
                ldsm4(aH[mf], ad);
                ldsm4(aL[mf], ad + 16384);
            }
            #pragma unroll
            for (int j = 0; j < 2; j++) {
                int n = bnn + j * 16;
                int u = kk * 2 + bus;
                uint32_t bd = base + 32768 + (n << 7) + ((u ^ (n & 7)) << 4);
                ldsm4(bH[j], bd);
                ldsm4(bL[j], bd + 16384);
            }
            MMA_TERMMAJOR(2);
        }
    }

    int r0b = m0 + wm * 32 + (lane >> 2);
    int cb  = n0 + wn * 32 + 2 * (lane & 3);
    #pragma unroll
    for (int mf = 0; mf < 2; mf++)
        #pragma unroll
        for (int nf = 0; nf < 4; nf++) {
            int c = cb + nf * 8;
            #pragma unroll
            for (int half = 0; half < 2; half++) {
                int r = r0b + mf * 16 + half * 8;
                size_t off = (size_t)r * N + c;
                epi_write<MODE>(acc[mf][nf][half * 2], acc[mf][nf][half * 2 + 1],
                                off, c, bias, res, Cf, Chi, Clo);
            }
        }
}

// ---------------- GEMM B: 128x64 tile, 256 threads, 2-stage, 2 CTAs/SM -------
// (round-6 best measured configuration, byte-for-byte)
constexpr int STAGE_B = 49152;
constexpr int SMEM_B_TOT = 2 * STAGE_B;     // 96KB -> 2 CTAs/SM

template<int MODE>
__global__ void __launch_bounds__(256, 2)
gemm_mma64(const bf16* __restrict__ Ahi, const bf16* __restrict__ Alo,
           const bf16* __restrict__ Bhi, const bf16* __restrict__ Blo,
           const float* __restrict__ bias, const float* __restrict__ res,
           float* __restrict__ Cf, bf16* __restrict__ Chi, bf16* __restrict__ Clo,
           int N, int K) {
    extern __shared__ __align__(128) char smraw[];
    uint32_t sb = smem_u32(smraw);

    int tid = threadIdx.x, wid = tid >> 5, lane = tid & 31;
    int wm = wid >> 1, wn = wid & 1;
    int m0 = blockIdx.y * 128, n0 = blockIdx.x * 64;

    float acc[2][4][4];
    #pragma unroll
    for (int i = 0; i < 2; i++)
        #pragma unroll
        for (int j = 0; j < 4; j++)
            #pragma unroll
            for (int r = 0; r < 4; r++) acc[i][j][r] = 0.0f;

    const int nk = K >> 6;

    auto load_stage = [&](int buf, int kt2) {
        int k0 = kt2 << 6;
        uint32_t sb0 = sb + buf * STAGE_B;
        #pragma unroll
        for (int t = 0; t < 4; t++) {
            int idx = tid + t * 256;
            int row = idx >> 3, u = idx & 7;
            uint32_t so = sb0 + (row << 7) + ((u ^ (row & 7)) << 4);
            size_t ea = (size_t)(m0 + row) * K + k0 + u * 8;
            CP16(so,         Ahi + ea);
            CP16(so + 16384, Alo + ea);
        }
        #pragma unroll
        for (int t = 0; t < 2; t++) {
            int idx = tid + t * 256;
            int row = idx >> 3, u = idx & 7;
            uint32_t so = sb0 + 32768 + (row << 7) + ((u ^ (row & 7)) << 4);
            size_t eb = (size_t)(n0 + row) * K + k0 + u * 8;
            CP16(so,        Bhi + eb);
            CP16(so + 8192, Blo + eb);
        }
    };

    load_stage(0, 0); CP_COMMIT();

    int lr = lane & 15, lu = lane >> 4;
    int bnn = wn * 32 + ((lane >> 4) << 3) + (lane & 7);
    int bus = (lane >> 3) & 1;

    for (int kt = 0; kt < nk; kt++) {
        CP_WAIT0();
        __syncthreads();
        if (kt + 1 < nk) { load_stage((kt + 1) & 1, kt + 1); CP_COMMIT(); }

        uint32_t base = sb + (kt & 1) * STAGE_B;
        #pragma unroll
        for (int kk = 0; kk < 4; kk++) {
            uint32_t aH[2][4], aL[2][4], bH[2][4], bL[2][4];
            #pragma unroll
            for (int mf = 0; mf < 2; mf++) {
                int r = wm * 32 + mf * 16 + lr;
                int u = kk * 2 + lu;
                uint32_t ad = base + (r << 7) + ((u ^ (r & 7)) << 4);
                ldsm4(aH[mf], ad);
                ldsm4(aL[mf], ad + 16384);
            }
            #pragma unroll
            for (int j = 0; j < 2; j++) {
                int n = bnn + j * 16;
                int u = kk * 2 + bus;
                uint32_t bd = base + 32768 + (n << 7) + ((u ^ (n & 7)) << 4);
                ldsm4(bH[j], bd);
                ldsm4(bL[j], bd + 8192);
            }
            MMA_TERMMAJOR(2);
        }
        __syncthreads();
    }

    int r0b = m0 + wm * 32 + (lane >> 2);
    int cb  = n0 + wn * 32 + 2 * (lane & 3);
    #pragma unroll
    for (int mf = 0; mf < 2; mf++)
        #pragma unroll
        for (int nf = 0; nf < 4; nf++) {
            int c = cb + nf * 8;
            #pragma unroll
            for (int half = 0; half < 2; half++) {
                int r = r0b + mf * 16 + half * 8;
                size_t off = (size_t)r * N + c;
                epi_write<MODE>(acc[mf][nf][half * 2], acc[mf][nf][half * 2 + 1],
                                off, c, bias, res, Cf, Chi, Clo);
            }
        }
}

// ---------------- fused attention: one block per (b, h), vectorized LDS -------
// Single query per warp pass (round-12 structure); float4 QK and sP reads.
// Accumulation order identical to the scalar version.
__global__ void __launch_bounds__(256)
attn_kernel(const float* __restrict__ qkv, const int* __restrict__ amask,
            bf16* __restrict__ ohi, bf16* __restrict__ olo) {
    __shared__ float sK[S_][DH_ + 4];     // 272B rows: float4-aligned
    __shared__ float sV[S_][DH_ + 4];
    __shared__ float sQ[8][DH_];
    __shared__ float sP[8][S_ + 3];       // 320B rows: float4-aligned
    __shared__ int   sM[S_];
    int h = blockIdx.x, b = blockIdx.y;
    int tid = threadIdx.x, lane = tid & 31, w = tid >> 5;

    for (int i = tid; i < S_ * DH_; i += 256) {
        int s = i >> 6, d = i & 63;
        size_t base = ((size_t)(b * S_ + s)) * QKVN + h * DH_ + d;
        sK[s][d] = qkv[base + D_];
        sV[s][d] = qkv[base + 2 * D_];
    }
    for (int i = tid; i < S_; i += 256)
        sM[i] = (i < NP_) ? 1 : amask[b * T_ + i - NP_];
    __syncthreads();

    for (int qi = w; qi < S_; qi += 8) {
        size_t qoff = ((size_t)(b * S_ + qi)) * QKVN + h * DH_;
        sQ[w][lane]      = qkv[qoff + lane];
        sQ[w][lane + 32] = qkv[qoff + lane + 32];
        __syncwarp();
        int nj = qi + 1;
        float sc[3];
        #pragma unroll
        for (int t = 0; t < 3; t++) {
            int j = lane + 32 * t;
            float dsum = -3.0e38f;
            if (j < nj) {
                dsum = 0.0f;
                #pragma unroll
                for (int d4 = 0; d4 < DH_ / 4; d4++) {
                    float4 qv = *(const float4*)&sQ[w][d4 * 4];
                    float4 kv = *(const float4*)&sK[j][d4 * 4];
                    dsum += qv.x * kv.x;
                    dsum += qv.y * kv.y;
                    dsum += qv.z * kv.z;
                    dsum += qv.w * kv.w;
                }
                if (sM[j] == 0) dsum = -1.0e30f;
            }
            sc[t] = dsum;
        }
        float m = fmaxf(sc[0], fmaxf(sc[1], sc[2]));
        #pragma unroll
        for (int o2 = 16; o2 > 0; o2 >>= 1) m = fmaxf(m, __shfl_xor_sync(0xffffffffu, m, o2));
        float e[3], esum = 0.0f;
        #pragma unroll
        for (int t = 0; t < 3; t++) {
            int j = lane + 32 * t;
            e[t] = (j < nj) ? __expf(sc[t] - m) : 0.0f;
            esum += e[t];
        }
        #pragma unroll
        for (int o2 = 16; o2 > 0; o2 >>= 1) esum += __shfl_xor_sync(0xffffffffu, esum, o2);
        float inv = 1.0f / esum;
        #pragma unroll
        for (int t = 0; t < 3; t++) {
            int j = lane + 32 * t;
            if (j < nj) sP[w][j] = e[t] * inv;
        }
        __syncwarp();
        float a0 = 0.0f, a1 = 0.0f;
        int nj4 = nj & ~3;
        for (int j = 0; j < nj4; j += 4) {
            float4 p4 = *(const float4*)&sP[w][j];
            a0 += p4.x * sV[j][lane];     a1 += p4.x * sV[j][lane + 32];
            a0 += p4.y * sV[j + 1][lane]; a1 += p4.y * sV[j + 1][lane + 32];
            a0 += p4.z * sV[j + 2][lane]; a1 += p4.z * sV[j + 2][lane + 32];
            a0 += p4.w * sV[j + 3][lane]; a1 += p4.w * sV[j + 3][lane + 32];
        }
        for (int j = nj4; j < nj; j++) {
            float p = sP[w][j];
            a0 += p * sV[j][lane];
            a1 += p * sV[j][lane + 32];
        }
        size_t ooff = ((size_t)(b * S_ + qi)) * D_ + h * DH_;
        bf16 h0 = __float2bfloat16(a0);
        ohi[ooff + lane] = h0;
        olo[ooff + lane] = __float2bfloat16(a0 - __bfloat162float(h0));
        bf16 h1 = __float2bfloat16(a1);
        ohi[ooff + lane + 32] = h1;
        olo[ooff + lane + 32] = __float2bfloat16(a1 - __bfloat162float(h1));
        __syncwarp();
    }
}

// ---------------- final: argmax gather + layernorm -> out ----------------
__device__ __forceinline__ float2 block_sum2(float s, float ss) {
    __shared__ float sh1[4], sh2[4];
    int lane = threadIdx.x & 31, w = threadIdx.x >> 5;
    #pragma unroll
    for (int o = 16; o > 0; o >>= 1) {
        s  += __shfl_down_sync(0xffffffffu, s,  o);
        ss += __shfl_down_sync(0xffffffffu, ss, o);
    }
    if (lane == 0) { sh1[w] = s; sh2[w] = ss; }
    __syncthreads();
    return make_float2(sh1[0] + sh1[1] + sh1[2] + sh1[3],
                       sh2[0] + sh2[1] + sh2[2] + sh2[3]);
}

__global__ void __launch_bounds__(128)
final_kernel(const float* __restrict__ x, const int* __restrict__ tok,
             const float* __restrict__ g, const float* __restrict__ bb,
             float* __restrict__ out) {
    int b = blockIdx.x, tid = threadIdx.x;
    __shared__ int sval[128];
    __shared__ int srow;
    sval[tid] = (tid < T_) ? tok[b * T_ + tid] : (-2147483647 - 1);
    __syncthreads();
    if (tid == 0) {
        int best = sval[0], bi = 0;
        for (int t = 1; t < T_; t++)
            if (sval[t] > best) { best = sval[t]; bi = t; }
        srow = bi + NP_;
    }
    __syncthreads();
    int row = b * S_ + srow;
    float4 vv = ((const float4*)(x + (size_t)row * D_))[tid];
    float s  = vv.x + vv.y + vv.z + vv.w;
    float ss = vv.x * vv.x + vv.y * vv.y + vv.z * vv.z + vv.w * vv.w;
    float2 tot = block_sum2(s, ss);
    float mean = tot.x * (1.0f / D_);
    float var  = tot.y * (1.0f / D_) - mean * mean;
    float rstd = rsqrtf(var + 1e-5f);
    float4 gv = ((const float4*)g)[tid];
    float4 bv = ((const float4*)bb)[tid];
    float4 ov;
    ov.x = (vv.x - mean) * rstd * gv.x + bv.x;
    ov.y = (vv.y - mean) * rstd * gv.y + bv.y;
    ov.z = (vv.z - mean) * rstd * gv.z + bv.z;
    ov.w = (vv.w - mean) * rstd * gv.w + bv.w;
    ((float4*)(out + (size_t)b * D_))[tid] = ov;
}

// ---------------- launch ----------------
extern "C" void kernel_launch(void* const* d_in, const int* in_sizes, int n_in,
                              void* d_out, int out_size) {
    (void)in_sizes; (void)n_in; (void)out_size;
    const int*   tok   = (const int*)  d_in[0];
    const int*   amask = (const int*)  d_in[1];
    const float* gp    = (const float*)d_in[2];
    const float* sp    = (const float*)d_in[3];
    const float* temb  = (const float*)d_in[4];
    const float* pemb  = (const float*)d_in[5];
    const float* ln1g  = (const float*)d_in[6];
    const float* ln1b  = (const float*)d_in[7];
    const float* Wq    = (const float*)d_in[8];
    const float* bq    = (const float*)d_in[9];
    const float* Wk    = (const float*)d_in[10];
    const float* bk    = (const float*)d_in[11];
    const float* Wv    = (const float*)d_in[12];
    const float* bv    = (const float*)d_in[13];
    const float* Wo    = (const float*)d_in[14];
    const float* bo    = (const float*)d_in[15];
    const float* ln2g  = (const float*)d_in[16];
    const float* ln2b  = (const float*)d_in[17];
    const float* W1    = (const float*)d_in[18];
    const float* b1    = (const float*)d_in[19];
    const float* W2    = (const float*)d_in[20];
    const float* b2    = (const float*)d_in[21];
    const float* lnfg  = (const float*)d_in[22];
    const float* lnfb  = (const float*)d_in[23];
    float* out = (float*)d_out;

    float *x, *qkv, *bqkv;
    bf16 *hhi, *hlo, *ohi, *olo, *fhi, *flo;
    bf16 *wqh, *wql, *woh, *wol, *w1h, *w1l, *w2h, *w2l;
    cudaGetSymbolAddress((void**)&x,   g_x);
    cudaGetSymbolAddress((void**)&hhi, g_hhi);
    cudaGetSymbolAddress((void**)&hlo, g_hlo);
    cudaGetSymbolAddress((void**)&qkv, g_qkv);
    cudaGetSymbolAddress((void**)&ohi, g_ohi);
    cudaGetSymbolAddress((void**)&olo, g_olo);
    cudaGetSymbolAddress((void**)&fhi, g_fhi);
    cudaGetSymbolAddress((void**)&flo, g_flo);
    cudaGetSymbolAddress((void**)&wqh, w_qkv_hi);
    cudaGetSymbolAddress((void**)&wql, w_qkv_lo);
    cudaGetSymbolAddress((void**)&woh, w_o_hi);
    cudaGetSymbolAddress((void**)&wol, w_o_lo);
    cudaGetSymbolAddress((void**)&w1h, w_1_hi);
    cudaGetSymbolAddress((void**)&w1l, w_1_lo);
    cudaGetSymbolAddress((void**)&w2h, w_2_hi);
    cudaGetSymbolAddress((void**)&w2l, w_2_lo);
    cudaGetSymbolAddress((void**)&bqkv, g_bqkv);

    cudaFuncSetAttribute(gemm_mma128<0>, cudaFuncAttributeMaxDynamicSharedMemorySize, SMEM_A_TOT);
    cudaFuncSetAttribute(gemm_mma128<2>, cudaFuncAttributeMaxDynamicSharedMemorySize, SMEM_A_TOT);
    cudaFuncSetAttribute(gemm_mma64<1>,  cudaFuncAttributeMaxDynamicSharedMemorySize, SMEM_B_TOT);

    prep_kernel<<<dim3(1024, 7, NL_), 256>>>(Wq, Wk, Wv, Wo, W1, W2, bq, bk, bv,
                                             wqh, wql, woh, wol, w1h, w1l, w2h, w2l, bqkv);
    embed_kernel<<<(B_ * S_ * D_) / 256, 256>>>(tok, gp, temb, pemb, x);

    dim3 gQKV(QKVN / 128, MROWS / 128);   // (12, 77)
    dim3 gFF (FF_  / 128, MROWS / 128);   // (16, 77)
    dim3 gD64(D_   / 64,  MROWS / 128);   // (8, 77) = 616 CTAs
    int lnGrid = MROWS / 8;               // 1232

    for (int i = 0; i < NL_; i++) {
        const float* p = nullptr; int bs = 0;
        if (i > 0) {
            if (i < DG_) { p = gp + (size_t)i * NP_ * D_;                 bs = DG_ * NP_ * D_; }
            else         { p = sp + (size_t)(i - (NL_ - DS_)) * NP_ * D_; bs = DS_ * NP_ * D_; }
        }
        ln_split_kernel<<<lnGrid, 256>>>(x, p, bs, ln1g + i * D_, ln1b + i * D_, hhi, hlo);
        gemm_mma128<0><<<gQKV, 512, SMEM_A_TOT>>>(hhi, hlo,
            wqh + (size_t)i * QKVN * D_, wql + (size_t)i * QKVN * D_,
            bqkv + i * QKVN, nullptr, qkv, nullptr, nullptr, QKVN, D_);
        attn_kernel<<<dim3(H_, B_), 256>>>(qkv, amask, ohi, olo);
        gemm_mma64<1><<<gD64, 256, SMEM_B_TOT>>>(ohi, olo,
            woh + (size_t)i * D_ * D_, wol + (size_t)i * D_ * D_,
            bo + i * D_, x, x, nullptr, nullptr, D_, D_);
        ln_split_kernel<<<lnGrid, 256>>>(x, nullptr, 0, ln2g + i * D_, ln2b + i * D_, hhi, hlo);
        gemm_mma128<2><<<gFF, 512, SMEM_A_TOT>>>(hhi, hlo,
            w1h + (size_t)i * FF_ * D_, w1l + (size_t)i * FF_ * D_,
            b1 + i * FF_, nullptr, nullptr, fhi, flo, FF_, D_);
        gemm_mma64<1><<<gD64, 256, SMEM_B_TOT>>>(fhi, flo,
            w2h + (size_t)i * D_ * FF_, w2l + (size_t)i * D_ * FF_,
            b2 + i * D_, x, x, nullptr, nullptr, D_, FF_);
    }
    final_kernel<<<B_, 128>>>(x, tok, lnfg, lnfb, out);
}

// round 15
// speedup vs baseline: 1.0768x; 1.0022x over previous
#include <cuda_runtime.h>
#include <cuda_bf16.h>
#include <math.h>
#include <stdint.h>

typedef __nv_bfloat16 bf16;

// ---------------- problem constants ----------------
constexpr int B_  = 128;
constexpr int T_  = 69;
constexpr int S_  = 77;
constexpr int D_  = 512;
constexpr int H_  = 8;
constexpr int DH_ = 64;
constexpr int NL_ = 12;
constexpr int FF_ = 2048;
constexpr int NP_ = 8;
constexpr int DG_ = 6;
constexpr int DS_ = 6;
constexpr int MROWS = B_ * S_;   // 9856 = 77 * 128
constexpr int QKVN  = 3 * D_;    // 1536

// ---------------- scratch (device globals; no runtime alloc) ----------------
__device__ __align__(128) float g_x  [MROWS * D_];
__device__ __align__(128) bf16  g_hhi[MROWS * D_];
__device__ __align__(128) bf16  g_hlo[MROWS * D_];
__device__ __align__(128) float g_qkv[MROWS * QKVN];
__device__ __align__(128) bf16  g_ohi[MROWS * D_];
__device__ __align__(128) bf16  g_olo[MROWS * D_];
__device__ __align__(128) bf16  g_fhi[MROWS * FF_];
__device__ __align__(128) bf16  g_flo[MROWS * FF_];

// transposed weight splits [layer][N][K] (K-major)
__device__ __align__(128) bf16  w_qkv_hi[NL_ * QKVN * D_];
__device__ __align__(128) bf16  w_qkv_lo[NL_ * QKVN * D_];
__device__ __align__(128) bf16  w_o_hi  [NL_ * D_ * D_];
__device__ __align__(128) bf16  w_o_lo  [NL_ * D_ * D_];
__device__ __align__(128) bf16  w_1_hi  [NL_ * FF_ * D_];
__device__ __align__(128) bf16  w_1_lo  [NL_ * FF_ * D_];
__device__ __align__(128) bf16  w_2_hi  [NL_ * D_ * FF_];
__device__ __align__(128) bf16  w_2_lo  [NL_ * D_ * FF_];
__device__ float g_bqkv  [NL_ * QKVN];

// ---------------- PTX helpers ----------------
__device__ __forceinline__ uint32_t smem_u32(const void* p) {
    uint32_t a;
    asm("{ .reg .u64 t; cvta.to.shared.u64 t, %1; cvt.u32.u64 %0, t; }" : "=r"(a) : "l"(p));
    return a;
}

#define CP16(saddr, gptr) \
    asm volatile("cp.async.cg.shared.global [%0], [%1], 16;" :: "r"(saddr), "l"(gptr) : "memory")
#define CP_COMMIT() asm volatile("cp.async.commit_group;" ::: "memory")
#define CP_WAIT1()  asm volatile("cp.async.wait_group 1;" ::: "memory")
#define CP_WAIT0()  asm volatile("cp.async.wait_group 0;" ::: "memory")

__device__ __forceinline__ void ldsm4(uint32_t* r, uint32_t addr) {
    asm volatile("ldmatrix.sync.aligned.m8n8.x4.shared.b16 {%0,%1,%2,%3}, [%4];"
                 : "=r"(r[0]), "=r"(r[1]), "=r"(r[2]), "=r"(r[3]) : "r"(addr));
}

__device__ __forceinline__ void mma16816(float* d, const uint32_t* a, const uint32_t* b) {
    asm volatile(
        "mma.sync.aligned.m16n8k16.row.col.f32.bf16.bf16.f32 "
        "{%0,%1,%2,%3}, {%4,%5,%6,%7}, {%8,%9}, {%0,%1,%2,%3};"
        : "+f"(d[0]), "+f"(d[1]), "+f"(d[2]), "+f"(d[3])
        : "r"(a[0]), "r"(a[1]), "r"(a[2]), "r"(a[3]), "r"(b[0]), "r"(b[1]));
}

// ---------------- unified preprocessing (1 launch) ----------------
__device__ __forceinline__ void tsplit_tile(const float* src, bf16* hi, bf16* lo,
                                            int K, int N, int n0, int k0, float scale) {
    __shared__ float t[32][33];
    int lx = threadIdx.x & 31, ly = threadIdx.x >> 5;
    #pragma unroll
    for (int i = ly; i < 32; i += 8)
        t[i][lx] = src[(size_t)(k0 + i) * N + n0 + lx];
    __syncthreads();
    #pragma unroll
    for (int i = ly; i < 32; i += 8) {
        float v = t[lx][i] * scale;
        size_t o = (size_t)(n0 + i) * K + k0 + lx;
        bf16 h = __float2bfloat16(v);
        hi[o] = h;
        lo[o] = __float2bfloat16(v - __bfloat162float(h));
    }
}

__global__ void __launch_bounds__(256)
prep_kernel(const float* __restrict__ Wq, const float* __restrict__ Wk,
            const float* __restrict__ Wv, const float* __restrict__ Wo,
            const float* __restrict__ W1, const float* __restrict__ W2,
            const float* __restrict__ bq, const float* __restrict__ bk,
            const float* __restrict__ bv,
            bf16* __restrict__ wqh, bf16* __restrict__ wql,
            bf16* __restrict__ woh, bf16* __restrict__ wol,
            bf16* __restrict__ w1h, bf16* __restrict__ w1l,
            bf16* __restrict__ w2h, bf16* __restrict__ w2l,
            float* __restrict__ bqkv) {
    int grp = blockIdx.y, layer = blockIdx.z, x = blockIdx.x;
    if (grp < 4) {
        if (x >= 256) return;
        int nt = x & 15, kt = x >> 4;
        const float* src; bf16 *hi, *lo;
        float sc = 1.0f;
        size_t lsrc = (size_t)layer * D_ * D_;
        if (grp == 0)      { src = Wq + lsrc; hi = wqh + (size_t)layer * QKVN * D_;            lo = wql + (size_t)layer * QKVN * D_; sc = 0.125f; }
        else if (grp == 1) { src = Wk + lsrc; hi = wqh + (size_t)layer * QKVN * D_ + D_ * D_;  lo = wql + (size_t)layer * QKVN * D_ + D_ * D_; }
        else if (grp == 2) { src = Wv + lsrc; hi = wqh + (size_t)layer * QKVN * D_ + 2*D_*D_;  lo = wql + (size_t)layer * QKVN * D_ + 2*D_*D_; }
        else               { src = Wo + lsrc; hi = woh + (size_t)layer * D_ * D_;              lo = wol + (size_t)layer * D_ * D_; }
        tsplit_tile(src, hi, lo, D_, D_, nt * 32, kt * 32, sc);
    } else if (grp == 4) {
        int nt = x & 63, kt = x >> 6;
        tsplit_tile(W1 + (size_t)layer * D_ * FF_,
                    w1h + (size_t)layer * FF_ * D_, w1l + (size_t)layer * FF_ * D_,
                    D_, FF_, nt * 32, kt * 32, 1.0f);
    } else if (grp == 5) {
        int nt = x & 15, kt = x >> 4;
        tsplit_tile(W2 + (size_t)layer * FF_ * D_,
                    w2h + (size_t)layer * D_ * FF_, w2l + (size_t)layer * D_ * FF_,
                    FF_, D_, nt * 32, kt * 32, 1.0f);
    } else {
        if (x >= 6) return;
        int idx = x * 256 + threadIdx.x;
        int n = idx;
        float v;
        if (n < D_)          v = bq[layer * D_ + n] * 0.125f;
        else if (n < 2 * D_) v = bk[layer * D_ + n - D_];
        else                 v = bv[layer * D_ + n - 2 * D_];
        bqkv[layer * QKVN + idx] = v;
    }
}

// ---------------- embedding ----------------
__global__ void embed_kernel(const int* __restrict__ tok, const float* __restrict__ gp,
                             const float* __restrict__ temb, const float* __restrict__ pemb,
                             float* __restrict__ x) {
    int idx = blockIdx.x * blockDim.x + threadIdx.x;
    int d  = idx & (D_ - 1);
    int bs = idx >> 9;
    int s  = bs % S_;
    int b  = bs / S_;
    float v;
    if (s == 0)            v = temb[(size_t)tok[b * T_] * D_ + d];
    else if (s <= NP_)     v = gp[((size_t)b * DG_) * NP_ * D_ + (s - 1) * D_ + d];
    else                   v = temb[(size_t)tok[b * T_ + (s - NP_)] * D_ + d];
    x[idx] = v + pemb[s * D_ + d];
}

// ---------------- layernorm, warp-per-row (+ fused prompt replace) ------------
__global__ void __launch_bounds__(256)
ln_split_kernel(float* __restrict__ x, const float* __restrict__ p, int bstride,
                const float* __restrict__ g, const float* __restrict__ bb,
                bf16* __restrict__ hi, bf16* __restrict__ lo) {
    int warp = threadIdx.x >> 5, lane = threadIdx.x & 31;
    int row = blockIdx.x * 8 + warp;
    if (row >= MROWS) return;
    int b = row / S_, s = row - b * S_;
    bool isp = (p != nullptr) && (s >= 1) && (s <= NP_);
    const float* srcrow = isp ? (p + (size_t)b * bstride + (size_t)(s - 1) * D_)
                              : (x + (size_t)row * D_);
    float4 v4[4];
    float su = 0.0f, ss = 0.0f;
    #pragma unroll
    for (int i = 0; i < 4; i++) {
        v4[i] = ((const float4*)srcrow)[lane + i * 32];
        su += v4[i].x + v4[i].y + v4[i].z + v4[i].w;
        ss += v4[i].x * v4[i].x + v4[i].y * v4[i].y + v4[i].z * v4[i].z + v4[i].w * v4[i].w;
    }
    if (isp) {
        #pragma unroll
        for (int i = 0; i < 4; i++)
            ((float4*)(x + (size_t)row * D_))[lane + i * 32] = v4[i];
    }
    #pragma unroll
    for (int o = 16; o > 0; o >>= 1) {
        su += __shfl_xor_sync(0xffffffffu, su, o);
        ss += __shfl_xor_sync(0xffffffffu, ss, o);
    }
    float mean = su * (1.0f / D_);
    float var  = ss * (1.0f / D_) - mean * mean;
    float rstd = rsqrtf(var + 1e-5f);
    #pragma unroll
    for (int i = 0; i < 4; i++) {
        float4 gv = ((const float4*)g)[lane + i * 32];
        float4 bv = ((const float4*)bb)[lane + i * 32];
        float o0 = (v4[i].x - mean) * rstd * gv.x + bv.x;
        float o1 = (v4[i].y - mean) * rstd * gv.y + bv.y;
        float o2 = (v4[i].z - mean) * rstd * gv.z + bv.z;
        float o3 = (v4[i].w - mean) * rstd * gv.w + bv.w;
        size_t o = (size_t)row * D_ + (lane + i * 32) * 4;
        __nv_bfloat162 h01 = __floats2bfloat162_rn(o0, o1);
        __nv_bfloat162 h23 = __floats2bfloat162_rn(o2, o3);
        *(__nv_bfloat162*)(hi + o)     = h01;
        *(__nv_bfloat162*)(hi + o + 2) = h23;
        float l0 = o0 - __low2float(h01);
        float l1 = o1 - __high2float(h01);
        float l2 = o2 - __low2float(h23);
        float l3 = o3 - __high2float(h23);
        *(__nv_bfloat162*)(lo + o)     = __floats2bfloat162_rn(l0, l1);
        *(__nv_bfloat162*)(lo + o + 2) = __floats2bfloat162_rn(l2, l3);
    }
}

// ---------------- shared epilogue ----------------
template<int MODE>
__device__ __forceinline__ void epi_write(float v0, float v1, size_t off, int c,
                                          const float* bias, const float* res,
                                          float* Cf, bf16* Chi, bf16* Clo) {
    v0 += bias[c]; v1 += bias[c + 1];
    if (MODE == 0) {
        *(float2*)(Cf + off) = make_float2(v0, v1);   // q-scale folded into weights
    } else if (MODE == 1) {
        float2 rr = *(const float2*)(res + off);
        *(float2*)(Cf + off) = make_float2(v0 + rr.x, v1 + rr.y);
    } else {
        v0 = v0 / (1.0f + __expf(-1.702f * v0));
        v1 = v1 / (1.0f + __expf(-1.702f * v1));
        __nv_bfloat162 h = __floats2bfloat162_rn(v0, v1);
        *(__nv_bfloat162*)(Chi + off) = h;
        float l0 = v0 - __low2float(h);
        float l1 = v1 - __high2float(h);
        *(__nv_bfloat162*)(Clo + off) = __floats2bfloat162_rn(l0, l1);
    }
}

// term-major MMA issue (round-6 exact), parameterized M-fragment count
#define MMA_TERMMAJOR(MF)                                                  \
    _Pragma("unroll")                                                      \
    for (int term = 0; term < 3; term++) {                                 \
        _Pragma("unroll")                                                  \
        for (int mf = 0; mf < MF; mf++) {                                  \
            _Pragma("unroll")                                              \
            for (int nf = 0; nf < 4; nf++) {                               \
                const uint32_t* a = (term == 2) ? aL[mf] : aH[mf];         \
                const uint32_t* b = (term == 1) ? &bL[nf >> 1][(nf & 1) * 2] \
                                                : &bH[nf >> 1][(nf & 1) * 2]; \
                mma16816(acc[mf][nf], a, b);                               \
            }                                                              \
        }                                                                  \
    }

// ---------------- GEMM A: 128x128 tile, 512 thr, 32x32 warp tiles, 3-stage ----
// (round-10 / round-6 best measured configuration, byte-for-byte)
constexpr int STAGE_A = 65536;
constexpr int SMEM_A_TOT = 3 * STAGE_A;     // 192KB

template<int MODE>
__global__ void __launch_bounds__(512)
gemm_mma128(const bf16* __restrict__ Ahi, const bf16* __restrict__ Alo,
            const bf16* __restrict__ Bhi, const bf16* __restrict__ Blo,
            const float* __restrict__ bias, const float* __restrict__ res,
            float* __restrict__ Cf, bf16* __restrict__ Chi, bf16* __restrict__ Clo,
            int N, int K) {
    extern __shared__ __align__(128) char smraw[];
    uint32_t sb = smem_u32(smraw);

    int tid = threadIdx.x, wid = tid >> 5, lane = tid & 31;
    int wm = wid >> 2, wn = wid & 3;
    int m0 = blockIdx.y * 128, n0 = blockIdx.x * 128;

    float acc[2][4][4];
    #pragma unroll
    for (int i = 0; i < 2; i++)
        #pragma unroll
        for (int j = 0; j < 4; j++)
            #pragma unroll
            for (int r = 0; r < 4; r++) acc[i][j][r] = 0.0f;

    const int nk = K >> 6;

    auto load_stage = [&](int buf, int kt2) {
        int k0 = kt2 << 6;
        uint32_t sb0 = sb + buf * STAGE_A;
        #pragma unroll
        for (int t = 0; t < 2; t++) {
            int idx = tid + t * 512;
            int row = idx >> 3, u = idx & 7;
            uint32_t so = sb0 + (row << 7) + ((u ^ (row & 7)) << 4);
            size_t ea = (size_t)(m0 + row) * K + k0 + u * 8;
            CP16(so,         Ahi + ea);
            CP16(so + 16384, Alo + ea);
        }
        #pragma unroll
        for (int t = 0; t < 2; t++) {
            int idx = tid + t * 512;
            int row = idx >> 3, u = idx & 7;
            uint32_t so = sb0 + 32768 + (row << 7) + ((u ^ (row & 7)) << 4);
            size_t eb = (size_t)(n0 + row) * K + k0 + u * 8;
            CP16(so,         Bhi + eb);
            CP16(so + 16384, Blo + eb);
        }
    };

    load_stage(0, 0); CP_COMMIT();
    load_stage(1, 1); CP_COMMIT();

    int lr = lane & 15, lu = lane >> 4;
    int bnn = wn * 32 + ((lane >> 4) << 3) + (lane & 7);
    int bus = (lane >> 3) & 1;

    for (int kt = 0; kt < nk; kt++) {
        if (kt < nk - 1) CP_WAIT1(); else CP_WAIT0();
        __syncthreads();
        if (kt + 2 < nk) { load_stage((kt + 2) % 3, kt + 2); CP_COMMIT(); }

        uint32_t base = sb + (kt % 3) * STAGE_A;
        #pragma unroll
        for (int kk = 0; kk < 4; kk++) {
            uint32_t aH[2][4], aL[2][4], bH[2][4], bL[2][4];
            #pragma unroll
            for (int mf = 0; mf < 2; mf++) {
                int r = wm * 32 + mf * 16 + lr;
                int u = kk * 2 + lu;
                uint32_t ad = base + (r << 7) + ((u ^ (r & 7)) << 4);
                ldsm4(aH[mf], ad);
                ldsm4(aL[mf], ad + 16384);
            }
            #pragma unroll
            for (int j = 0; j < 2; j++) {
                int n = bnn + j * 16;
                int u = kk * 2 + bus;
                uint32_t bd = base + 32768 + (n << 7) + ((u ^ (n & 7)) << 4);
                ldsm4(bH[j], bd);
                ldsm4(bL[j], bd + 16384);
            }
            MMA_TERMMAJOR(2);
        }
    }

    int r0b = m0 + wm * 32 + (lane >> 2);
    int cb  = n0 + wn * 32 + 2 * (lane & 3);
    #pragma unroll
    for (int mf = 0; mf < 2; mf++)
        #pragma unroll
        for (int nf = 0; nf < 4; nf++) {
            int c = cb + nf * 8;
            #pragma unroll
            for (int half = 0; half < 2; half++) {
                int r = r0b + mf * 16 + half * 8;
                size_t off = (size_t)r * N + c;
                epi_write<MODE>(acc[mf][nf][half * 2], acc[mf][nf][half * 2 + 1],
                                off, c, bias, res, Cf, Chi, Clo);
            }
        }
}

// ---------------- GEMM B: 128x64 tile, 256 threads, 2-stage, 2 CTAs/SM -------
// (round-6 best measured configuration, byte-for-byte)
constexpr int STAGE_B = 49152;
constexpr int SMEM_B_TOT = 2 * STAGE_B;     // 96KB -> 2 CTAs/SM

template<int MODE>
__global__ void __launch_bounds__(256, 2)
gemm_mma64(const bf16* __restrict__ Ahi, const bf16* __restrict__ Alo,
           const bf16* __restrict__ Bhi, const bf16* __restrict__ Blo,
           const float* __restrict__ bias, const float* __restrict__ res,
           float* __restrict__ Cf, bf16* __restrict__ Chi, bf16* __restrict__ Clo,
           int N, int K) {
    extern __shared__ __align__(128) char smraw[];
    uint32_t sb = smem_u32(smraw);

    int tid = threadIdx.x, wid = tid >> 5, lane = tid & 31;
    int wm = wid >> 1, wn = wid & 1;
    int m0 = blockIdx.y * 128, n0 = blockIdx.x * 64;

    float acc[2][4][4];
    #pragma unroll
    for (int i = 0; i < 2; i++)
        #pragma unroll
        for (int j = 0; j < 4; j++)
            #pragma unroll
            for (int r = 0; r < 4; r++) acc[i][j][r] = 0.0f;

    const int nk = K >> 6;

    auto load_stage = [&](int buf, int kt2) {
        int k0 = kt2 << 6;
        uint32_t sb0 = sb + buf * STAGE_B;
        #pragma unroll
        for (int t = 0; t < 4; t++) {
            int idx = tid + t * 256;
            int row = idx >> 3, u = idx & 7;
            uint32_t so = sb0 + (row << 7) + ((u ^ (row & 7)) << 4);
            size_t ea = (size_t)(m0 + row) * K + k0 + u * 8;
            CP16(so,         Ahi + ea);
            CP16(so + 16384, Alo + ea);
        }
        #pragma unroll
        for (int t = 0; t < 2; t++) {
            int idx = tid + t * 256;
            int row = idx >> 3, u = idx & 7;
            uint32_t so = sb0 + 32768 + (row << 7) + ((u ^ (row & 7)) << 4);
            size_t eb = (size_t)(n0 + row) * K + k0 + u * 8;
            CP16(so,        Bhi + eb);
            CP16(so + 8192, Blo + eb);
        }
    };

    load_stage(0, 0); CP_COMMIT();

    int lr = lane & 15, lu = lane >> 4;
    int bnn = wn * 32 + ((lane >> 4) << 3) + (lane & 7);
    int bus = (lane >> 3) & 1;

    for (int kt = 0; kt < nk; kt++) {
        CP_WAIT0();
        __syncthreads();
        if (kt + 1 < nk) { load_stage((kt + 1) & 1, kt + 1); CP_COMMIT(); }

        uint32_t base = sb + (kt & 1) * STAGE_B;
        #pragma unroll
        for (int kk = 0; kk < 4; kk++) {
            uint32_t aH[2][4], aL[2][4], bH[2][4], bL[2][4];
            #pragma unroll
            for (int mf = 0; mf < 2; mf++) {
                int r = wm * 32 + mf * 16 + lr;
                int u = kk * 2 + lu;
                uint32_t ad = base + (r << 7) + ((u ^ (r & 7)) << 4);
                ldsm4(aH[mf], ad);
                ldsm4(aL[mf], ad + 16384);
            }
            #pragma unroll
            for (int j = 0; j < 2; j++) {
                int n = bnn + j * 16;
                int u = kk * 2 + bus;
                uint32_t bd = base + 32768 + (n << 7) + ((u ^ (n & 7)) << 4);
                ldsm4(bH[j], bd);
                ldsm4(bL[j], bd + 8192);
            }
            MMA_TERMMAJOR(2);
        }
        __syncthreads();
    }

    int r0b = m0 + wm * 32 + (lane >> 2);
    int cb  = n0 + wn * 32 + 2 * (lane & 3);
    #pragma unroll
    for (int mf = 0; mf < 2; mf++)
        #pragma unroll
        for (int nf = 0; nf < 4; nf++) {
            int c = cb + nf * 8;
            #pragma unroll
            for (int half = 0; half < 2; half++) {
                int r = r0b + mf * 16 + half * 8;
                size_t off = (size_t)r * N + c;
                epi_write<MODE>(acc[mf][nf][half * 2], acc[mf][nf][half * 2 + 1],
                                off, c, bias, res, Cf, Chi, Clo);
            }
        }
}

// ---------------- fused attention: one block per (b, h), 512 threads ----------
// 16 warps/block, 4 blocks/SM -> 64 warps/SM (2x round-14 occupancy).
// Per-query arithmetic identical to round 14 (vectorized QK + sP).
constexpr int ATTN_KROW = DH_ + 4;   // 68 floats, float4-aligned rows
constexpr int ATTN_SMEM =
    (S_ * ATTN_KROW + S_ * DH_ + 16 * DH_ + 16 * 80) * 4 + S_ * 4;  // ~50.2 KB

__global__ void __launch_bounds__(512)
attn_kernel(const float* __restrict__ qkv, const int* __restrict__ amask,
            bf16* __restrict__ ohi, bf16* __restrict__ olo) {
    extern __shared__ __align__(16) float smf[];
    float* sK = smf;                            // [S_][68]
    float* sV = sK + S_ * ATTN_KROW;            // [S_][64]
    float* sQ = sV + S_ * DH_;                  // [16][64]
    float* sP = sQ + 16 * DH_;                  // [16][80]
    int*   sM = (int*)(sP + 16 * 80);           // [S_]
    int h = blockIdx.x, b = blockIdx.y;
    int tid = threadIdx.x, lane = tid & 31, w = tid >> 5;

    for (int i = tid; i < S_ * DH_; i += 512) {
        int s = i >> 6, d = i & 63;
        size_t base = ((size_t)(b * S_ + s)) * QKVN + h * DH_ + d;
        sK[s * ATTN_KROW + d] = qkv[base + D_];
        sV[s * DH_ + d]       = qkv[base + 2 * D_];
    }
    for (int i = tid; i < S_; i += 512)
        sM[i] = (i < NP_) ? 1 : amask[b * T_ + i - NP_];
    __syncthreads();

    float* sQw = sQ + w * DH_;
    float* sPw = sP + w * 80;

    for (int qi = w; qi < S_; qi += 16) {
        size_t qoff = ((size_t)(b * S_ + qi)) * QKVN + h * DH_;
        sQw[lane]      = qkv[qoff + lane];
        sQw[lane + 32] = qkv[qoff + lane + 32];
        __syncwarp();
        int nj = qi + 1;
        float sc[3];
        #pragma unroll
        for (int t = 0; t < 3; t++) {
            int j = lane + 32 * t;
            float dsum = -3.0e38f;
            if (j < nj) {
                dsum = 0.0f;
                const float* kr = sK + j * ATTN_KROW;
                #pragma unroll
                for (int d4 = 0; d4 < DH_ / 4; d4++) {
                    float4 qv = *(const float4*)&sQw[d4 * 4];
                    float4 kv = *(const float4*)&kr[d4 * 4];
                    dsum += qv.x * kv.x;
                    dsum += qv.y * kv.y;
                    dsum += qv.z * kv.z;
                    dsum += qv.w * kv.w;
                }
                if (sM[j] == 0) dsum = -1.0e30f;
            }
            sc[t] = dsum;
        }
        float m = fmaxf(sc[0], fmaxf(sc[1], sc[2]));
        #pragma unroll
        for (int o2 = 16; o2 > 0; o2 >>= 1) m = fmaxf(m, __shfl_xor_sync(0xffffffffu, m, o2));
        float e[3], esum = 0.0f;
        #pragma unroll
        for (int t = 0; t < 3; t++) {
            int j = lane + 32 * t;
            e[t] = (j < nj) ? __expf(sc[t] - m) : 0.0f;
            esum += e[t];
        }
        #pragma unroll
        for (int o2 = 16; o2 > 0; o2 >>= 1) esum += __shfl_xor_sync(0xffffffffu, esum, o2);
        float inv = 1.0f / esum;
        #pragma unroll
        for (int t = 0; t < 3; t++) {
            int j = lane + 32 * t;
            if (j < nj) sPw[j] = e[t] * inv;
        }
        __syncwarp();
        float a0 = 0.0f, a1 = 0.0f;
        int nj4 = nj & ~3;
        for (int j = 0; j < nj4; j += 4) {
            float4 p4 = *(const float4*)&sPw[j];
            a0 += p4.x * sV[j * DH_ + lane];       a1 += p4.x * sV[j * DH_ + lane + 32];
            a0 += p4.y * sV[(j + 1) * DH_ + lane]; a1 += p4.y * sV[(j + 1) * DH_ + lane + 32];
            a0 += p4.z * sV[(j + 2) * DH_ + lane]; a1 += p4.z * sV[(j + 2) * DH_ + lane + 32];
            a0 += p4.w * sV[(j + 3) * DH_ + lane]; a1 += p4.w * sV[(j + 3) * DH_ + lane + 32];
        }
        for (int j = nj4; j < nj; j++) {
            float p = sPw[j];
            a0 += p * sV[j * DH_ + lane];
            a1 += p * sV[j * DH_ + lane + 32];
        }
        size_t ooff = ((size_t)(b * S_ + qi)) * D_ + h * DH_;
        bf16 h0 = __float2bfloat16(a0);
        ohi[ooff + lane] = h0;
        olo[ooff + lane] = __float2bfloat16(a0 - __bfloat162float(h0));
        bf16 h1 = __float2bfloat16(a1);
        ohi[ooff + lane + 32] = h1;
        olo[ooff + lane + 32] = __float2bfloat16(a1 - __bfloat162float(h1));
        __syncwarp();
    }
}

// ---------------- final: argmax gather + layernorm -> out ----------------
__device__ __forceinline__ float2 block_sum2(float s, float ss) {
    __shared__ float sh1[4], sh2[4];
    int lane = threadIdx.x & 31, w = threadIdx.x >> 5;
    #pragma unroll
    for (int o = 16; o > 0; o >>= 1) {
        s  += __shfl_down_sync(0xffffffffu, s,  o);
        ss += __shfl_down_sync(0xffffffffu, ss, o);
    }
    if (lane == 0) { sh1[w] = s; sh2[w] = ss; }
    __syncthreads();
    return make_float2(sh1[0] + sh1[1] + sh1[2] + sh1[3],
                       sh2[0] + sh2[1] + sh2[2] + sh2[3]);
}

__global__ void __launch_bounds__(128)
final_kernel(const float* __restrict__ x, const int* __restrict__ tok,
             const float* __restrict__ g, const float* __restrict__ bb,
             float* __restrict__ out) {
    int b = blockIdx.x, tid = threadIdx.x;
    __shared__ int sval[128];
    __shared__ int srow;
    sval[tid] = (tid < T_) ? tok[b * T_ + tid] : (-2147483647 - 1);
    __syncthreads();
    if (tid == 0) {
        int best = sval[0], bi = 0;
        for (int t = 1; t < T_; t++)
            if (sval[t] > best) { best = sval[t]; bi = t; }
        srow = bi + NP_;
    }
    __syncthreads();
    int row = b * S_ + srow;
    float4 vv = ((const float4*)(x + (size_t)row * D_))[tid];
    float s  = vv.x + vv.y + vv.z + vv.w;
    float ss = vv.x * vv.x + vv.y * vv.y + vv.z * vv.z + vv.w * vv.w;
    float2 tot = block_sum2(s, ss);
    float mean = tot.x * (1.0f / D_);
    float var  = tot.y * (1.0f / D_) - mean * mean;
    float rstd = rsqrtf(var + 1e-5f);
    float4 gv = ((const float4*)g)[tid];
    float4 bv = ((const float4*)bb)[tid];
    float4 ov;
    ov.x = (vv.x - mean) * rstd * gv.x + bv.x;
    ov.y = (vv.y - mean) * rstd * gv.y + bv.y;
    ov.z = (vv.z - mean) * rstd * gv.z + bv.z;
    ov.w = (vv.w - mean) * rstd * gv.w + bv.w;
    ((float4*)(out + (size_t)b * D_))[tid] = ov;
}

// ---------------- launch ----------------
extern "C" void kernel_launch(void* const* d_in, const int* in_sizes, int n_in,
                              void* d_out, int out_size) {
    (void)in_sizes; (void)n_in; (void)out_size;
    const int*   tok   = (const int*)  d_in[0];
    const int*   amask = (const int*)  d_in[1];
    const float* gp    = (const float*)d_in[2];
    const float* sp    = (const float*)d_in[3];
    const float* temb  = (const float*)d_in[4];
    const float* pemb  = (const float*)d_in[5];
    const float* ln1g  = (const float*)d_in[6];
    const float* ln1b  = (const float*)d_in[7];
    const float* Wq    = (const float*)d_in[8];
    const float* bq    = (const float*)d_in[9];
    const float* Wk    = (const float*)d_in[10];
    const float* bk    = (const float*)d_in[11];
    const float* Wv    = (const float*)d_in[12];
    const float* bv    = (const float*)d_in[13];
    const float* Wo    = (const float*)d_in[14];
    const float* bo    = (const float*)d_in[15];
    const float* ln2g  = (const float*)d_in[16];
    const float* ln2b  = (const float*)d_in[17];
    const float* W1    = (const float*)d_in[18];
    const float* b1    = (const float*)d_in[19];
    const float* W2    = (const float*)d_in[20];
    const float* b2    = (const float*)d_in[21];
    const float* lnfg  = (const float*)d_in[22];
    const float* lnfb  = (const float*)d_in[23];
    float* out = (float*)d_out;

    float *x, *qkv, *bqkv;
    bf16 *hhi, *hlo, *ohi, *olo, *fhi, *flo;
    bf16 *wqh, *wql, *woh, *wol, *w1h, *w1l, *w2h, *w2l;
    cudaGetSymbolAddress((void**)&x,   g_x);
    cudaGetSymbolAddress((void**)&hhi, g_hhi);
    cudaGetSymbolAddress((void**)&hlo, g_hlo);
    cudaGetSymbolAddress((void**)&qkv, g_qkv);
    cudaGetSymbolAddress((void**)&ohi, g_ohi);
    cudaGetSymbolAddress((void**)&olo, g_olo);
    cudaGetSymbolAddress((void**)&fhi, g_fhi);
    cudaGetSymbolAddress((void**)&flo, g_flo);
    cudaGetSymbolAddress((void**)&wqh, w_qkv_hi);
    cudaGetSymbolAddress((void**)&wql, w_qkv_lo);
    cudaGetSymbolAddress((void**)&woh, w_o_hi);
    cudaGetSymbolAddress((void**)&wol, w_o_lo);
    cudaGetSymbolAddress((void**)&w1h, w_1_hi);
    cudaGetSymbolAddress((void**)&w1l, w_1_lo);
    cudaGetSymbolAddress((void**)&w2h, w_2_hi);
    cudaGetSymbolAddress((void**)&w2l, w_2_lo);
    cudaGetSymbolAddress((void**)&bqkv, g_bqkv);

    cudaFuncSetAttribute(gemm_mma128<0>, cudaFuncAttributeMaxDynamicSharedMemorySize, SMEM_A_TOT);
    cudaFuncSetAttribute(gemm_mma128<2>, cudaFuncAttributeMaxDynamicSharedMemorySize, SMEM_A_TOT);
    cudaFuncSetAttribute(gemm_mma64<1>,  cudaFuncAttributeMaxDynamicSharedMemorySize, SMEM_B_TOT);
    cudaFuncSetAttribute(attn_kernel,    cudaFuncAttributeMaxDynamicSharedMemorySize, ATTN_SMEM);

    prep_kernel<<<dim3(1024, 7, NL_), 256>>>(Wq, Wk, Wv, Wo, W1, W2, bq, bk, bv,
                                             wqh, wql, woh, wol, w1h, w1l, w2h, w2l, bqkv);
    embed_kernel<<<(B_ * S_ * D_) / 256, 256>>>(tok, gp, temb, pemb, x);

    dim3 gQKV(QKVN / 128, MROWS / 128);   // (12, 77)
    dim3 gFF (FF_  / 128, MROWS / 128);   // (16, 77)
    dim3 gD64(D_   / 64,  MROWS / 128);   // (8, 77) = 616 CTAs
    int lnGrid = MROWS / 8;               // 1232

    for (int i = 0; i < NL_; i++) {
        const float* p = nullptr; int bs = 0;
        if (i > 0) {
            if (i < DG_) { p = gp + (size_t)i * NP_ * D_;                 bs = DG_ * NP_ * D_; }
            else         { p = sp + (size_t)(i - (NL_ - DS_)) * NP_ * D_; bs = DS_ * NP_ * D_; }
        }
        ln_split_kernel<<<lnGrid, 256>>>(x, p, bs, ln1g + i * D_, ln1b + i * D_, hhi, hlo);
        gemm_mma128<0><<<gQKV, 512, SMEM_A_TOT>>>(hhi, hlo,
            wqh + (size_t)i * QKVN * D_, wql + (size_t)i * QKVN * D_,
            bqkv + i * QKVN, nullptr, qkv, nullptr, nullptr, QKVN, D_);
        attn_kernel<<<dim3(H_, B_), 512, ATTN_SMEM>>>(qkv, amask, ohi, olo);
        gemm_mma64<1><<<gD64, 256, SMEM_B_TOT>>>(ohi, olo,
            woh + (size_t)i * D_ * D_, wol + (size_t)i * D_ * D_,
            bo + i * D_, x, x, nullptr, nullptr, D_, D_);
        ln_split_kernel<<<lnGrid, 256>>>(x, nullptr, 0, ln2g + i * D_, ln2b + i * D_, hhi, hlo);
        gemm_mma128<2><<<gFF, 512, SMEM_A_TOT>>>(hhi, hlo,
            w1h + (size_t)i * FF_ * D_, w1l + (size_t)i * FF_ * D_,
            b1 + i * FF_, nullptr, nullptr, fhi, flo, FF_, D_);
        gemm_mma64<1><<<gD64, 256, SMEM_B_TOT>>>(fhi, flo,
            w2h + (size_t)i * D_ * FF_, w2l + (size_t)i * D_ * FF_,
            b2 + i * D_, x, x, nullptr, nullptr, D_, FF_);
    }
    final_kernel<<<B_, 128>>>(x, tok, lnfg, lnfb, out);
}

// round 16
// speedup vs baseline: 1.0843x; 1.0070x over previous
#include <cuda_runtime.h>
#include <cuda_bf16.h>
#include <math.h>
#include <stdint.h>

typedef __nv_bfloat16 bf16;

// ---------------- problem constants ----------------
constexpr int B_  = 128;
constexpr int T_  = 69;
constexpr int S_  = 77;
constexpr int D_  = 512;
constexpr int H_  = 8;
constexpr int DH_ = 64;
constexpr int NL_ = 12;
constexpr int FF_ = 2048;
constexpr int NP_ = 8;
constexpr int DG_ = 6;
constexpr int DS_ = 6;
constexpr int MROWS = B_ * S_;   // 9856 = 77 * 128
constexpr int QKVN  = 3 * D_;    // 1536

// ---------------- scratch (device globals; no runtime alloc) ----------------
__device__ __align__(128) float g_x  [MROWS * D_];
__device__ __align__(128) bf16  g_hhi[MROWS * D_];
__device__ __align__(128) bf16  g_hlo[MROWS * D_];
__device__ __align__(128) float g_qkv[MROWS * QKVN];
__device__ __align__(128) bf16  g_ohi[MROWS * D_];
__device__ __align__(128) bf16  g_olo[MROWS * D_];
__device__ __align__(128) bf16  g_fhi[MROWS * FF_];
__device__ __align__(128) bf16  g_flo[MROWS * FF_];

// transposed weight splits [layer][N][K] (K-major)
__device__ __align__(128) bf16  w_qkv_hi[NL_ * QKVN * D_];
__device__ __align__(128) bf16  w_qkv_lo[NL_ * QKVN * D_];
__device__ __align__(128) bf16  w_o_hi  [NL_ * D_ * D_];
__device__ __align__(128) bf16  w_o_lo  [NL_ * D_ * D_];
__device__ __align__(128) bf16  w_1_hi  [NL_ * FF_ * D_];
__device__ __align__(128) bf16  w_1_lo  [NL_ * FF_ * D_];
__device__ __align__(128) bf16  w_2_hi  [NL_ * D_ * FF_];
__device__ __align__(128) bf16  w_2_lo  [NL_ * D_ * FF_];
__device__ float g_bqkv  [NL_ * QKVN];

// ---------------- PTX helpers ----------------
__device__ __forceinline__ uint32_t smem_u32(const void* p) {
    uint32_t a;
    asm("{ .reg .u64 t; cvta.to.shared.u64 t, %1; cvt.u32.u64 %0, t; }" : "=r"(a) : "l"(p));
    return a;
}

#define CP16(saddr, gptr) \
    asm volatile("cp.async.cg.shared.global [%0], [%1], 16;" :: "r"(saddr), "l"(gptr) : "memory")
#define CP_COMMIT() asm volatile("cp.async.commit_group;" ::: "memory")
#define CP_WAIT1()  asm volatile("cp.async.wait_group 1;" ::: "memory")
#define CP_WAIT0()  asm volatile("cp.async.wait_group 0;" ::: "memory")

__device__ __forceinline__ void ldsm4(uint32_t* r, uint32_t addr) {
    asm volatile("ldmatrix.sync.aligned.m8n8.x4.shared.b16 {%0,%1,%2,%3}, [%4];"
                 : "=r"(r[0]), "=r"(r[1]), "=r"(r[2]), "=r"(r[3]) : "r"(addr));
}

__device__ __forceinline__ void mma16816(float* d, const uint32_t* a, const uint32_t* b) {
    asm volatile(
        "mma.sync.aligned.m16n8k16.row.col.f32.bf16.bf16.f32 "
        "{%0,%1,%2,%3}, {%4,%5,%6,%7}, {%8,%9}, {%0,%1,%2,%3};"
        : "+f"(d[0]), "+f"(d[1]), "+f"(d[2]), "+f"(d[3])
        : "r"(a[0]), "r"(a[1]), "r"(a[2]), "r"(a[3]), "r"(b[0]), "r"(b[1]));
}

// ---------------- unified preprocessing (1 launch) ----------------
__device__ __forceinline__ void tsplit_tile(const float* src, bf16* hi, bf16* lo,
                                            int K, int N, int n0, int k0, float scale) {
    __shared__ float t[32][33];
    int lx = threadIdx.x & 31, ly = threadIdx.x >> 5;
    #pragma unroll
    for (int i = ly; i < 32; i += 8)
        t[i][lx] = src[(size_t)(k0 + i) * N + n0 + lx];
    __syncthreads();
    #pragma unroll
    for (int i = ly; i < 32; i += 8) {
        float v = t[lx][i] * scale;
        size_t o = (size_t)(n0 + i) * K + k0 + lx;
        bf16 h = __float2bfloat16(v);
        hi[o] = h;
        lo[o] = __float2bfloat16(v - __bfloat162float(h));
    }
}

__global__ void __launch_bounds__(256)
prep_kernel(const float* __restrict__ Wq, const float* __restrict__ Wk,
            const float* __restrict__ Wv, const float* __restrict__ Wo,
            const float* __restrict__ W1, const float* __restrict__ W2,
            const float* __restrict__ bq, const float* __restrict__ bk,
            const float* __restrict__ bv,
            bf16* __restrict__ wqh, bf16* __restrict__ wql,
            bf16* __restrict__ woh, bf16* __restrict__ wol,
            bf16* __restrict__ w1h, bf16* __restrict__ w1l,
            bf16* __restrict__ w2h, bf16* __restrict__ w2l,
            float* __restrict__ bqkv) {
    int grp = blockIdx.y, layer = blockIdx.z, x = blockIdx.x;
    if (grp < 4) {
        if (x >= 256) return;
        int nt = x & 15, kt = x >> 4;
        const float* src; bf16 *hi, *lo;
        float sc = 1.0f;
        size_t lsrc = (size_t)layer * D_ * D_;
        if (grp == 0)      { src = Wq + lsrc; hi = wqh + (size_t)layer * QKVN * D_;            lo = wql + (size_t)layer * QKVN * D_; sc = 0.125f; }
        else if (grp == 1) { src = Wk + lsrc; hi = wqh + (size_t)layer * QKVN * D_ + D_ * D_;  lo = wql + (size_t)layer * QKVN * D_ + D_ * D_; }
        else if (grp == 2) { src = Wv + lsrc; hi = wqh + (size_t)layer * QKVN * D_ + 2*D_*D_;  lo = wql + (size_t)layer * QKVN * D_ + 2*D_*D_; }
        else               { src = Wo + lsrc; hi = woh + (size_t)layer * D_ * D_;              lo = wol + (size_t)layer * D_ * D_; }
        tsplit_tile(src, hi, lo, D_, D_, nt * 32, kt * 32, sc);
    } else if (grp == 4) {
        int nt = x & 63, kt = x >> 6;
        tsplit_tile(W1 + (size_t)layer * D_ * FF_,
                    w1h + (size_t)layer * FF_ * D_, w1l + (size_t)layer * FF_ * D_,
                    D_, FF_, nt * 32, kt * 32, 1.0f);
    } else if (grp == 5) {
        int nt = x & 15, kt = x >> 4;
        tsplit_tile(W2 + (size_t)layer * FF_ * D_,
                    w2h + (size_t)layer * D_ * FF_, w2l + (size_t)layer * D_ * FF_,
                    FF_, D_, nt * 32, kt * 32, 1.0f);
    } else {
        if (x >= 6) return;
        int idx = x * 256 + threadIdx.x;
        int n = idx;
        float v;
        if (n < D_)          v = bq[layer * D_ + n] * 0.125f;
        else if (n < 2 * D_) v = bk[layer * D_ + n - D_];
        else                 v = bv[layer * D_ + n - 2 * D_];
        bqkv[layer * QKVN + idx] = v;
    }
}

// ---------------- embedding ----------------
__global__ void embed_kernel(const int* __restrict__ tok, const float* __restrict__ gp,
                             const float* __restrict__ temb, const float* __restrict__ pemb,
                             float* __restrict__ x) {
    int idx = blockIdx.x * blockDim.x + threadIdx.x;
    int d  = idx & (D_ - 1);
    int bs = idx >> 9;
    int s  = bs % S_;
    int b  = bs / S_;
    float v;
    if (s == 0)            v = temb[(size_t)tok[b * T_] * D_ + d];
    else if (s <= NP_)     v = gp[((size_t)b * DG_) * NP_ * D_ + (s - 1) * D_ + d];
    else                   v = temb[(size_t)tok[b * T_ + (s - NP_)] * D_ + d];
    x[idx] = v + pemb[s * D_ + d];
}

// ---------------- layernorm, warp-per-row (+ fused prompt replace) ------------
__global__ void __launch_bounds__(256)
ln_split_kernel(float* __restrict__ x, const float* __restrict__ p, int bstride,
                const float* __restrict__ g, const float* __restrict__ bb,
                bf16* __restrict__ hi, bf16* __restrict__ lo) {
    int warp = threadIdx.x >> 5, lane = threadIdx.x & 31;
    int row = blockIdx.x * 8 + warp;
    if (row >= MROWS) return;
    int b = row / S_, s = row - b * S_;
    bool isp = (p != nullptr) && (s >= 1) && (s <= NP_);
    const float* srcrow = isp ? (p + (size_t)b * bstride + (size_t)(s - 1) * D_)
                              : (x + (size_t)row * D_);
    float4 v4[4];
    float su = 0.0f, ss = 0.0f;
    #pragma unroll
    for (int i = 0; i < 4; i++) {
        v4[i] = ((const float4*)srcrow)[lane + i * 32];
        su += v4[i].x + v4[i].y + v4[i].z + v4[i].w;
        ss += v4[i].x * v4[i].x + v4[i].y * v4[i].y + v4[i].z * v4[i].z + v4[i].w * v4[i].w;
    }
    if (isp) {
        #pragma unroll
        for (int i = 0; i < 4; i++)
            ((float4*)(x + (size_t)row * D_))[lane + i * 32] = v4[i];
    }
    #pragma unroll
    for (int o = 16; o > 0; o >>= 1) {
        su += __shfl_xor_sync(0xffffffffu, su, o);
        ss += __shfl_xor_sync(0xffffffffu, ss, o);
    }
    float mean = su * (1.0f / D_);
    float var  = ss * (1.0f / D_) - mean * mean;
    float rstd = rsqrtf(var + 1e-5f);
    #pragma unroll
    for (int i = 0; i < 4; i++) {
        float4 gv = ((const float4*)g)[lane + i * 32];
        float4 bv = ((const float4*)bb)[lane + i * 32];
        float o0 = (v4[i].x - mean) * rstd * gv.x + bv.x;
        float o1 = (v4[i].y - mean) * rstd * gv.y + bv.y;
        float o2 = (v4[i].z - mean) * rstd * gv.z + bv.z;
        float o3 = (v4[i].w - mean) * rstd * gv.w + bv.w;
        size_t o = (size_t)row * D_ + (lane + i * 32) * 4;
        __nv_bfloat162 h01 = __floats2bfloat162_rn(o0, o1);
        __nv_bfloat162 h23 = __floats2bfloat162_rn(o2, o3);
        *(__nv_bfloat162*)(hi + o)     = h01;
        *(__nv_bfloat162*)(hi + o + 2) = h23;
        float l0 = o0 - __low2float(h01);
        float l1 = o1 - __high2float(h01);
        float l2 = o2 - __low2float(h23);
        float l3 = o3 - __high2float(h23);
        *(__nv_bfloat162*)(lo + o)     = __floats2bfloat162_rn(l0, l1);
        *(__nv_bfloat162*)(lo + o + 2) = __floats2bfloat162_rn(l2, l3);
    }
}

// ---------------- shared epilogue ----------------
template<int MODE>
__device__ __forceinline__ void epi_write(float v0, float v1, size_t off, int c,
                                          const float* bias, const float* res,
                                          float* Cf, bf16* Chi, bf16* Clo) {
    v0 += bias[c]; v1 += bias[c + 1];
    if (MODE == 0) {
        *(float2*)(Cf + off) = make_float2(v0, v1);   // q-scale folded into weights
    } else if (MODE == 1) {
        float2 rr = *(const float2*)(res + off);
        *(float2*)(Cf + off) = make_float2(v0 + rr.x, v1 + rr.y);
    } else {
        v0 = v0 / (1.0f + __expf(-1.702f * v0));
        v1 = v1 / (1.0f + __expf(-1.702f * v1));
        __nv_bfloat162 h = __floats2bfloat162_rn(v0, v1);
        *(__nv_bfloat162*)(Chi + off) = h;
        float l0 = v0 - __low2float(h);
        float l1 = v1 - __high2float(h);
        *(__nv_bfloat162*)(Clo + off) = __floats2bfloat162_rn(l0, l1);
    }
}

// term-major MMA issue (round-6 exact), parameterized M-fragment count
#define MMA_TERMMAJOR(MF)                                                  \
    _Pragma("unroll")                                                      \
    for (int term = 0; term < 3; term++) {                                 \
        _Pragma("unroll")                                                  \
        for (int mf = 0; mf < MF; mf++) {                                  \
            _Pragma("unroll")                                              \
            for (int nf = 0; nf < 4; nf++) {                               \
                const uint32_t* a = (term == 2) ? aL[mf] : aH[mf];         \
                const uint32_t* b = (term == 1) ? &bL[nf >> 1][(nf & 1) * 2] \
                                                : &bH[nf >> 1][(nf & 1) * 2]; \
                mma16816(acc[mf][nf], a, b);                               \
            }                                                              \
        }                                                                  \
    }

// ---------------- GEMM A: 128x128 tile, 512 thr, 32x32 warp tiles, 3-stage ----
// (round-10 / round-6 best measured configuration, byte-for-byte)
constexpr int STAGE_A = 65536;
constexpr int SMEM_A_TOT = 3 * STAGE_A;     // 192KB

template<int MODE>
__global__ void __launch_bounds__(512)
gemm_mma128(const bf16* __restrict__ Ahi, const bf16* __restrict__ Alo,
            const bf16* __restrict__ Bhi, const bf16* __restrict__ Blo,
            const float* __restrict__ bias, const float* __restrict__ res,
            float* __restrict__ Cf, bf16* __restrict__ Chi, bf16* __restrict__ Clo,
            int N, int K) {
    extern __shared__ __align__(128) char smraw[];
    uint32_t sb = smem_u32(smraw);

    int tid = threadIdx.x, wid = tid >> 5, lane = tid & 31;
    int wm = wid >> 2, wn = wid & 3;
    int m0 = blockIdx.y * 128, n0 = blockIdx.x * 128;

    float acc[2][4][4];
    #pragma unroll
    for (int i = 0; i < 2; i++)
        #pragma unroll
        for (int j = 0; j < 4; j++)
            #pragma unroll
            for (int r = 0; r < 4; r++) acc[i][j][r] = 0.0f;

    const int nk = K >> 6;

    auto load_stage = [&](int buf, int kt2) {
        int k0 = kt2 << 6;
        uint32_t sb0 = sb + buf * STAGE_A;
        #pragma unroll
        for (int t = 0; t < 2; t++) {
            int idx = tid + t * 512;
            int row = idx >> 3, u = idx & 7;
            uint32_t so = sb0 + (row << 7) + ((u ^ (row & 7)) << 4);
            size_t ea = (size_t)(m0 + row) * K + k0 + u * 8;
            CP16(so,         Ahi + ea);
            CP16(so + 16384, Alo + ea);
        }
        #pragma unroll
        for (int t = 0; t < 2; t++) {
            int idx = tid + t * 512;
            int row = idx >> 3, u = idx & 7;
            uint32_t so = sb0 + 32768 + (row << 7) + ((u ^ (row & 7)) << 4);
            size_t eb = (size_t)(n0 + row) * K + k0 + u * 8;
            CP16(so,         Bhi + eb);
            CP16(so + 16384, Blo + eb);
        }
    };

    load_stage(0, 0); CP_COMMIT();
    load_stage(1, 1); CP_COMMIT();

    int lr = lane & 15, lu = lane >> 4;
    int bnn = wn * 32 + ((lane >> 4) << 3) + (lane & 7);
    int bus = (lane >> 3) & 1;

    for (int kt = 0; kt < nk; kt++) {
        if (kt < nk - 1) CP_WAIT1(); else CP_WAIT0();
        __syncthreads();
        if (kt + 2 < nk) { load_stage((kt + 2) % 3, kt + 2); CP_COMMIT(); }

        uint32_t base = sb + (kt % 3) * STAGE_A;
        #pragma unroll
        for (int kk = 0; kk < 4; kk++) {
            uint32_t aH[2][4], aL[2][4], bH[2][4], bL[2][4];
            #pragma unroll
            for (int mf = 0; mf < 2; mf++) {
                int r = wm * 32 + mf * 16 + lr;
                int u = kk * 2 + lu;
                uint32_t ad = base + (r << 7) + ((u ^ (r & 7)) << 4);
                ldsm4(aH[mf], ad);
                ldsm4(aL[mf], ad + 16384);
            }
            #pragma unroll
            for (int j = 0; j < 2; j++) {
                int n = bnn + j * 16;
                int u = kk * 2 + bus;
                uint32_t bd = base + 32768 + (n << 7) + ((u ^ (n & 7)) << 4);
                ldsm4(bH[j], bd);
                ldsm4(bL[j], bd + 16384);
            }
            MMA_TERMMAJOR(2);
        }
    }

    int r0b = m0 + wm * 32 + (lane >> 2);
    int cb  = n0 + wn * 32 + 2 * (lane & 3);
    #pragma unroll
    for (int mf = 0; mf < 2; mf++)
        #pragma unroll
        for (int nf = 0; nf < 4; nf++) {
            int c = cb + nf * 8;
            #pragma unroll
            for (int half = 0; half < 2; half++) {
                int r = r0b + mf * 16 + half * 8;
                size_t off = (size_t)r * N + c;
                epi_write<MODE>(acc[mf][nf][half * 2], acc[mf][nf][half * 2 + 1],
                                off, c, bias, res, Cf, Chi, Clo);
            }
        }
}

// ---------------- GEMM B: 128x64 tile, 256 threads, 2-stage, 2 CTAs/SM -------
// (round-6 best measured configuration, byte-for-byte)
constexpr int STAGE_B = 49152;
constexpr int SMEM_B_TOT = 2 * STAGE_B;     // 96KB -> 2 CTAs/SM

template<int MODE>
__global__ void __launch_bounds__(256, 2)
gemm_mma64(const bf16* __restrict__ Ahi, const bf16* __restrict__ Alo,
           const bf16* __restrict__ Bhi, const bf16* __restrict__ Blo,
           const float* __restrict__ bias, const float* __restrict__ res,
           float* __restrict__ Cf, bf16* __restrict__ Chi, bf16* __restrict__ Clo,
           int N, int K) {
    extern __shared__ __align__(128) char smraw[];
    uint32_t sb = smem_u32(smraw);

    int tid = threadIdx.x, wid = tid >> 5, lane = tid & 31;
    int wm = wid >> 1, wn = wid & 1;
    int m0 = blockIdx.y * 128, n0 = blockIdx.x * 64;

    float acc[2][4][4];
    #pragma unroll
    for (int i = 0; i < 2; i++)
        #pragma unroll
        for (int j = 0; j < 4; j++)
            #pragma unroll
            for (int r = 0; r < 4; r++) acc[i][j][r] = 0.0f;

    const int nk = K >> 6;

    auto load_stage = [&](int buf, int kt2) {
        int k0 = kt2 << 6;
        uint32_t sb0 = sb + buf * STAGE_B;
        #pragma unroll
        for (int t = 0; t < 4; t++) {
            int idx = tid + t * 256;
            int row = idx >> 3, u = idx & 7;
            uint32_t so = sb0 + (row << 7) + ((u ^ (row & 7)) << 4);
            size_t ea = (size_t)(m0 + row) * K + k0 + u * 8;
            CP16(so,         Ahi + ea);
            CP16(so + 16384, Alo + ea);
        }
        #pragma unroll
        for (int t = 0; t < 2; t++) {
            int idx = tid + t * 256;
            int row = idx >> 3, u = idx & 7;
            uint32_t so = sb0 + 32768 + (row << 7) + ((u ^ (row & 7)) << 4);
            size_t eb = (size_t)(n0 + row) * K + k0 + u * 8;
            CP16(so,        Bhi + eb);
            CP16(so + 8192, Blo + eb);
        }
    };

    load_stage(0, 0); CP_COMMIT();

    int lr = lane & 15, lu = lane >> 4;
    int bnn = wn * 32 + ((lane >> 4) << 3) + (lane & 7);
    int bus = (lane >> 3) & 1;

    for (int kt = 0; kt < nk; kt++) {
        CP_WAIT0();
        __syncthreads();
        if (kt + 1 < nk) { load_stage((kt + 1) & 1, kt + 1); CP_COMMIT(); }

        uint32_t base = sb + (kt & 1) * STAGE_B;
        #pragma unroll
        for (int kk = 0; kk < 4; kk++) {
            uint32_t aH[2][4], aL[2][4], bH[2][4], bL[2][4];
            #pragma unroll
            for (int mf = 0; mf < 2; mf++) {
                int r = wm * 32 + mf * 16 + lr;
                int u = kk * 2 + lu;
                uint32_t ad = base + (r << 7) + ((u ^ (r & 7)) << 4);
                ldsm4(aH[mf], ad);
                ldsm4(aL[mf], ad + 16384);
            }
            #pragma unroll
            for (int j = 0; j < 2; j++) {
                int n = bnn + j * 16;
                int u = kk * 2 + bus;
                uint32_t bd = base + 32768 + (n << 7) + ((u ^ (n & 7)) << 4);
                ldsm4(bH[j], bd);
                ldsm4(bL[j], bd + 8192);
            }
            MMA_TERMMAJOR(2);
        }
        __syncthreads();
    }

    int r0b = m0 + wm * 32 + (lane >> 2);
    int cb  = n0 + wn * 32 + 2 * (lane & 3);
    #pragma unroll
    for (int mf = 0; mf < 2; mf++)
        #pragma unroll
        for (int nf = 0; nf < 4; nf++) {
            int c = cb + nf * 8;
            #pragma unroll
            for (int half = 0; half < 2; half++) {
                int r = r0b + mf * 16 + half * 8;
                size_t off = (size_t)r * N + c;
                epi_write<MODE>(acc[mf][nf][half * 2], acc[mf][nf][half * 2 + 1],
                                off, c, bias, res, Cf, Chi, Clo);
            }
        }
}

// ---------------- fused attention: one block per (b, h), 512 threads ----------
// Round-15 structure; K/V global->SMEM loads vectorized to float4 (bit-identical).
constexpr int ATTN_KROW = DH_ + 4;   // 68 floats, float4-aligned rows
constexpr int ATTN_SMEM =
    (S_ * ATTN_KROW + S_ * DH_ + 16 * DH_ + 16 * 80) * 4 + S_ * 4;  // ~50.2 KB

__global__ void __launch_bounds__(512)
attn_kernel(const float* __restrict__ qkv, const int* __restrict__ amask,
            bf16* __restrict__ ohi, bf16* __restrict__ olo) {
    extern __shared__ __align__(16) float smf[];
    float* sK = smf;                            // [S_][68]
    float* sV = sK + S_ * ATTN_KROW;            // [S_][64]
    float* sQ = sV + S_ * DH_;                  // [16][64]
    float* sP = sQ + 16 * DH_;                  // [16][80]
    int*   sM = (int*)(sP + 16 * 80);           // [S_]
    int h = blockIdx.x, b = blockIdx.y;
    int tid = threadIdx.x, lane = tid & 31, w = tid >> 5;

    // vectorized K/V load: S_*DH_/4 = 1232 float4 transfers
    for (int i = tid; i < S_ * (DH_ / 4); i += 512) {
        int s = i >> 4, d4 = i & 15;
        size_t base4 = (((size_t)(b * S_ + s)) * QKVN + h * DH_) / 4 + d4;
        float4 kv = ((const float4*)qkv)[base4 + D_ / 4];
        float4 vv = ((const float4*)qkv)[base4 + 2 * D_ / 4];
        *(float4*)&sK[s * ATTN_KROW + d4 * 4] = kv;
        *(float4*)&sV[s * DH_ + d4 * 4]       = vv;
    }
    for (int i = tid; i < S_; i += 512)
        sM[i] = (i < NP_) ? 1 : amask[b * T_ + i - NP_];
    __syncthreads();

    float* sQw = sQ + w * DH_;
    float* sPw = sP + w * 80;

    for (int qi = w; qi < S_; qi += 16) {
        size_t qoff = ((size_t)(b * S_ + qi)) * QKVN + h * DH_;
        sQw[lane]      = qkv[qoff + lane];
        sQw[lane + 32] = qkv[qoff + lane + 32];
        __syncwarp();
        int nj = qi + 1;
        float sc[3];
        #pragma unroll
        for (int t = 0; t < 3; t++) {
            int j = lane + 32 * t;
            float dsum = -3.0e38f;
            if (j < nj) {
                dsum = 0.0f;
                const float* kr = sK + j * ATTN_KROW;
                #pragma unroll
                for (int d4 = 0; d4 < DH_ / 4; d4++) {
                    float4 qv = *(const float4*)&sQw[d4 * 4];
                    float4 kv = *(const float4*)&kr[d4 * 4];
                    dsum += qv.x * kv.x;
                    dsum += qv.y * kv.y;
                    dsum += qv.z * kv.z;
                    dsum += qv.w * kv.w;
                }
                if (sM[j] == 0) dsum = -1.0e30f;
            }
            sc[t] = dsum;
        }
        float m = fmaxf(sc[0], fmaxf(sc[1], sc[2]));
        #pragma unroll
        for (int o2 = 16; o2 > 0; o2 >>= 1) m = fmaxf(m, __shfl_xor_sync(0xffffffffu, m, o2));
        float e[3], esum = 0.0f;
        #pragma unroll
        for (int t = 0; t < 3; t++) {
            int j = lane + 32 * t;
            e[t] = (j < nj) ? __expf(sc[t] - m) : 0.0f;
            esum += e[t];
        }
        #pragma unroll
        for (int o2 = 16; o2 > 0; o2 >>= 1) esum += __shfl_xor_sync(0xffffffffu, esum, o2);
        float inv = 1.0f / esum;
        #pragma unroll
        for (int t = 0; t < 3; t++) {
            int j = lane + 32 * t;
            if (j < nj) sPw[j] = e[t] * inv;
        }
        __syncwarp();
        float a0 = 0.0f, a1 = 0.0f;
        int nj4 = nj & ~3;
        for (int j = 0; j < nj4; j += 4) {
            float4 p4 = *(const float4*)&sPw[j];
            a0 += p4.x * sV[j * DH_ + lane];       a1 += p4.x * sV[j * DH_ + lane + 32];
            a0 += p4.y * sV[(j + 1) * DH_ + lane]; a1 += p4.y * sV[(j + 1) * DH_ + lane + 32];
            a0 += p4.z * sV[(j + 2) * DH_ + lane]; a1 += p4.z * sV[(j + 2) * DH_ + lane + 32];
            a0 += p4.w * sV[(j + 3) * DH_ + lane]; a1 += p4.w * sV[(j + 3) * DH_ + lane + 32];
        }
        for (int j = nj4; j < nj; j++) {
            float p = sPw[j];
            a0 += p * sV[j * DH_ + lane];
            a1 += p * sV[j * DH_ + lane + 32];
        }
        size_t ooff = ((size_t)(b * S_ + qi)) * D_ + h * DH_;
        bf16 h0 = __float2bfloat16(a0);
        ohi[ooff + lane] = h0;
        olo[ooff + lane] = __float2bfloat16(a0 - __bfloat162float(h0));
        bf16 h1 = __float2bfloat16(a1);
        ohi[ooff + lane + 32] = h1;
        olo[ooff + lane + 32] = __float2bfloat16(a1 - __bfloat162float(h1));
        __syncwarp();
    }
}

// ---------------- final: argmax gather + layernorm -> out ----------------
__device__ __forceinline__ float2 block_sum2(float s, float ss) {
    __shared__ float sh1[4], sh2[4];
    int lane = threadIdx.x & 31, w = threadIdx.x >> 5;
    #pragma unroll
    for (int o = 16; o > 0; o >>= 1) {
        s  += __shfl_down_sync(0xffffffffu, s,  o);
        ss += __shfl_down_sync(0xffffffffu, ss, o);
    }
    if (lane == 0) { sh1[w] = s; sh2[w] = ss; }
    __syncthreads();
    return make_float2(sh1[0] + sh1[1] + sh1[2] + sh1[3],
                       sh2[0] + sh2[1] + sh2[2] + sh2[3]);
}

__global__ void __launch_bounds__(128)
final_kernel(const float* __restrict__ x, const int* __restrict__ tok,
             const float* __restrict__ g, const float* __restrict__ bb,
             float* __restrict__ out) {
    int b = blockIdx.x, tid = threadIdx.x;
    __shared__ int sval[128];
    __shared__ int srow;
    sval[tid] = (tid < T_) ? tok[b * T_ + tid] : (-2147483647 - 1);
    __syncthreads();
    if (tid == 0) {
        int best = sval[0], bi = 0;
        for (int t = 1; t < T_; t++)
            if (sval[t] > best) { best = sval[t]; bi = t; }
        srow = bi + NP_;
    }
    __syncthreads();
    int row = b * S_ + srow;
    float4 vv = ((const float4*)(x + (size_t)row * D_))[tid];
    float s  = vv.x + vv.y + vv.z + vv.w;
    float ss = vv.x * vv.x + vv.y * vv.y + vv.z * vv.z + vv.w * vv.w;
    float2 tot = block_sum2(s, ss);
    float mean = tot.x * (1.0f / D_);
    float var  = tot.y * (1.0f / D_) - mean * mean;
    float rstd = rsqrtf(var + 1e-5f);
    float4 gv = ((const float4*)g)[tid];
    float4 bv = ((const float4*)bb)[tid];
    float4 ov;
    ov.x = (vv.x - mean) * rstd * gv.x + bv.x;
    ov.y = (vv.y - mean) * rstd * gv.y + bv.y;
    ov.z = (vv.z - mean) * rstd * gv.z + bv.z;
    ov.w = (vv.w - mean) * rstd * gv.w + bv.w;
    ((float4*)(out + (size_t)b * D_))[tid] = ov;
}

// ---------------- launch ----------------
extern "C" void kernel_launch(void* const* d_in, const int* in_sizes, int n_in,
                              void* d_out, int out_size) {
    (void)in_sizes; (void)n_in; (void)out_size;
    const int*   tok   = (const int*)  d_in[0];
    const int*   amask = (const int*)  d_in[1];
    const float* gp    = (const float*)d_in[2];
    const float* sp    = (const float*)d_in[3];
    const float* temb  = (const float*)d_in[4];
    const float* pemb  = (const float*)d_in[5];
    const float* ln1g  = (const float*)d_in[6];
    const float* ln1b  = (const float*)d_in[7];
    const float* Wq    = (const float*)d_in[8];
    const float* bq    = (const float*)d_in[9];
    const float* Wk    = (const float*)d_in[10];
    const float* bk    = (const float*)d_in[11];
    const float* Wv    = (const float*)d_in[12];
    const float* bv    = (const float*)d_in[13];
    const float* Wo    = (const float*)d_in[14];
    const float* bo    = (const float*)d_in[15];
    const float* ln2g  = (const float*)d_in[16];
    const float* ln2b  = (const float*)d_in[17];
    const float* W1    = (const float*)d_in[18];
    const float* b1    = (const float*)d_in[19];
    const float* W2    = (const float*)d_in[20];
    const float* b2    = (const float*)d_in[21];
    const float* lnfg  = (const float*)d_in[22];
    const float* lnfb  = (const float*)d_in[23];
    float* out = (float*)d_out;

    float *x, *qkv, *bqkv;
    bf16 *hhi, *hlo, *ohi, *olo, *fhi, *flo;
    bf16 *wqh, *wql, *woh, *wol, *w1h, *w1l, *w2h, *w2l;
    cudaGetSymbolAddress((void**)&x,   g_x);
    cudaGetSymbolAddress((void**)&hhi, g_hhi);
    cudaGetSymbolAddress((void**)&hlo, g_hlo);
    cudaGetSymbolAddress((void**)&qkv, g_qkv);
    cudaGetSymbolAddress((void**)&ohi, g_ohi);
    cudaGetSymbolAddress((void**)&olo, g_olo);
    cudaGetSymbolAddress((void**)&fhi, g_fhi);
    cudaGetSymbolAddress((void**)&flo, g_flo);
    cudaGetSymbolAddress((void**)&wqh, w_qkv_hi);
    cudaGetSymbolAddress((void**)&wql, w_qkv_lo);
    cudaGetSymbolAddress((void**)&woh, w_o_hi);
    cudaGetSymbolAddress((void**)&wol, w_o_lo);
    cudaGetSymbolAddress((void**)&w1h, w_1_hi);
    cudaGetSymbolAddress((void**)&w1l, w_1_lo);
    cudaGetSymbolAddress((void**)&w2h, w_2_hi);
    cudaGetSymbolAddress((void**)&w2l, w_2_lo);
    cudaGetSymbolAddress((void**)&bqkv, g_bqkv);

    cudaFuncSetAttribute(gemm_mma128<0>, cudaFuncAttributeMaxDynamicSharedMemorySize, SMEM_A_TOT);
    cudaFuncSetAttribute(gemm_mma128<2>, cudaFuncAttributeMaxDynamicSharedMemorySize, SMEM_A_TOT);
    cudaFuncSetAttribute(gemm_mma64<1>,  cudaFuncAttributeMaxDynamicSharedMemorySize, SMEM_B_TOT);
    cudaFuncSetAttribute(attn_kernel,    cudaFuncAttributeMaxDynamicSharedMemorySize, ATTN_SMEM);

    prep_kernel<<<dim3(1024, 7, NL_), 256>>>(Wq, Wk, Wv, Wo, W1, W2, bq, bk, bv,
                                             wqh, wql, woh, wol, w1h, w1l, w2h, w2l, bqkv);
    embed_kernel<<<(B_ * S_ * D_) / 256, 256>>>(tok, gp, temb, pemb, x);

    dim3 gQKV(QKVN / 128, MROWS / 128);   // (12, 77)
    dim3 gFF (FF_  / 128, MROWS / 128);   // (16, 77)
    dim3 gD64(D_   / 64,  MROWS / 128);   // (8, 77) = 616 CTAs
    int lnGrid = MROWS / 8;               // 1232

    for (int i = 0; i < NL_; i++) {
        const float* p = nullptr; int bs = 0;
        if (i > 0) {
            if (i < DG_) { p = gp + (size_t)i * NP_ * D_;                 bs = DG_ * NP_ * D_; }
            else         { p = sp + (size_t)(i - (NL_ - DS_)) * NP_ * D_; bs = DS_ * NP_ * D_; }
        }
        ln_split_kernel<<<lnGrid, 256>>>(x, p, bs, ln1g + i * D_, ln1b + i * D_, hhi, hlo);
        gemm_mma128<0><<<gQKV, 512, SMEM_A_TOT>>>(hhi, hlo,
            wqh + (size_t)i * QKVN * D_, wql + (size_t)i * QKVN * D_,
            bqkv + i * QKVN, nullptr, qkv, nullptr, nullptr, QKVN, D_);
        attn_kernel<<<dim3(H_, B_), 512, ATTN_SMEM>>>(qkv, amask, ohi, olo);
        gemm_mma64<1><<<gD64, 256, SMEM_B_TOT>>>(ohi, olo,
            woh + (size_t)i * D_ * D_, wol + (size_t)i * D_ * D_,
            bo + i * D_, x, x, nullptr, nullptr, D_, D_);
        ln_split_kernel<<<lnGrid, 256>>>(x, nullptr, 0, ln2g + i * D_, ln2b + i * D_, hhi, hlo);
        gemm_mma128<2><<<gFF, 512, SMEM_A_TOT>>>(hhi, hlo,
            w1h + (size_t)i * FF_ * D_, w1l + (size_t)i * FF_ * D_,
            b1 + i * FF_, nullptr, nullptr, fhi, flo, FF_, D_);
        gemm_mma64<1><<<gD64, 256, SMEM_B_TOT>>>(fhi, flo,
            w2h + (size_t)i * D_ * FF_, w2l + (size_t)i * D_ * FF_,
            b2 + i * D_, x, x, nullptr, nullptr, D_, FF_);
    }
    final_kernel<<<B_, 128>>>(x, tok, lnfg, lnfb, out);
}

// round 17
// speedup vs baseline: 1.0869x; 1.0024x over previous
#include <cuda_runtime.h>
#include <cuda_bf16.h>
#include <math.h>
#include <stdint.h>

typedef __nv_bfloat16 bf16;

// ---------------- problem constants ----------------
constexpr int B_  = 128;
constexpr int T_  = 69;
constexpr int S_  = 77;
constexpr int D_  = 512;
constexpr int H_  = 8;
constexpr int DH_ = 64;
constexpr int NL_ = 12;
constexpr int FF_ = 2048;
constexpr int NP_ = 8;
constexpr int DG_ = 6;
constexpr int DS_ = 6;
constexpr int MROWS = B_ * S_;   // 9856 = 77 * 128
constexpr int QKVN  = 3 * D_;    // 1536

// ---------------- scratch (device globals; no runtime alloc) ----------------
__device__ __align__(128) float g_x  [MROWS * D_];
__device__ __align__(128) bf16  g_hhi[MROWS * D_];
__device__ __align__(128) bf16  g_hlo[MROWS * D_];
__device__ __align__(128) float g_qkv[MROWS * QKVN];
__device__ __align__(128) bf16  g_ohi[MROWS * D_];
__device__ __align__(128) bf16  g_olo[MROWS * D_];
__device__ __align__(128) bf16  g_fhi[MROWS * FF_];
__device__ __align__(128) bf16  g_flo[MROWS * FF_];

// transposed weight splits [layer][N][K] (K-major)
__device__ __align__(128) bf16  w_qkv_hi[NL_ * QKVN * D_];
__device__ __align__(128) bf16  w_qkv_lo[NL_ * QKVN * D_];
__device__ __align__(128) bf16  w_o_hi  [NL_ * D_ * D_];
__device__ __align__(128) bf16  w_o_lo  [NL_ * D_ * D_];
__device__ __align__(128) bf16  w_1_hi  [NL_ * FF_ * D_];
__device__ __align__(128) bf16  w_1_lo  [NL_ * FF_ * D_];
__device__ __align__(128) bf16  w_2_hi  [NL_ * D_ * FF_];
__device__ __align__(128) bf16  w_2_lo  [NL_ * D_ * FF_];
__device__ float g_bqkv  [NL_ * QKVN];

// ---------------- PTX helpers ----------------
__device__ __forceinline__ uint32_t smem_u32(const void* p) {
    uint32_t a;
    asm("{ .reg .u64 t; cvta.to.shared.u64 t, %1; cvt.u32.u64 %0, t; }" : "=r"(a) : "l"(p));
    return a;
}

#define CP16(saddr, gptr) \
    asm volatile("cp.async.cg.shared.global [%0], [%1], 16;" :: "r"(saddr), "l"(gptr) : "memory")
#define CP_COMMIT() asm volatile("cp.async.commit_group;" ::: "memory")
#define CP_WAIT1()  asm volatile("cp.async.wait_group 1;" ::: "memory")
#define CP_WAIT0()  asm volatile("cp.async.wait_group 0;" ::: "memory")

__device__ __forceinline__ void ldsm4(uint32_t* r, uint32_t addr) {
    asm volatile("ldmatrix.sync.aligned.m8n8.x4.shared.b16 {%0,%1,%2,%3}, [%4];"
                 : "=r"(r[0]), "=r"(r[1]), "=r"(r[2]), "=r"(r[3]) : "r"(addr));
}

__device__ __forceinline__ void mma16816(float* d, const uint32_t* a, const uint32_t* b) {
    asm volatile(
        "mma.sync.aligned.m16n8k16.row.col.f32.bf16.bf16.f32 "
        "{%0,%1,%2,%3}, {%4,%5,%6,%7}, {%8,%9}, {%0,%1,%2,%3};"
        : "+f"(d[0]), "+f"(d[1]), "+f"(d[2]), "+f"(d[3])
        : "r"(a[0]), "r"(a[1]), "r"(a[2]), "r"(a[3]), "r"(b[0]), "r"(b[1]));
}

// ---------------- unified preprocessing (1 launch) ----------------
__device__ __forceinline__ void tsplit_tile(const float* src, bf16* hi, bf16* lo,
                                            int K, int N, int n0, int k0, float scale) {
    __shared__ float t[32][33];
    int lx = threadIdx.x & 31, ly = threadIdx.x >> 5;
    #pragma unroll
    for (int i = ly; i < 32; i += 8)
        t[i][lx] = src[(size_t)(k0 + i) * N + n0 + lx];
    __syncthreads();
    #pragma unroll
    for (int i = ly; i < 32; i += 8) {
        float v = t[lx][i] * scale;
        size_t o = (size_t)(n0 + i) * K + k0 + lx;
        bf16 h = __float2bfloat16(v);
        hi[o] = h;
        lo[o] = __float2bfloat16(v - __bfloat162float(h));
    }
}

__global__ void __launch_bounds__(256)
prep_kernel(const float* __restrict__ Wq, const float* __restrict__ Wk,
            const float* __restrict__ Wv, const float* __restrict__ Wo,
            const float* __restrict__ W1, const float* __restrict__ W2,
            const float* __restrict__ bq, const float* __restrict__ bk,
            const float* __restrict__ bv,
            bf16* __restrict__ wqh, bf16* __restrict__ wql,
            bf16* __restrict__ woh, bf16* __restrict__ wol,
            bf16* __restrict__ w1h, bf16* __restrict__ w1l,
            bf16* __restrict__ w2h, bf16* __restrict__ w2l,
            float* __restrict__ bqkv) {
    int grp = blockIdx.y, layer = blockIdx.z, x = blockIdx.x;
    if (grp < 4) {
        if (x >= 256) return;
        int nt = x & 15, kt = x >> 4;
        const float* src; bf16 *hi, *lo;
        float sc = 1.0f;
        size_t lsrc = (size_t)layer * D_ * D_;
        if (grp == 0)      { src = Wq + lsrc; hi = wqh + (size_t)layer * QKVN * D_;            lo = wql + (size_t)layer * QKVN * D_; sc = 0.125f; }
        else if (grp == 1) { src = Wk + lsrc; hi = wqh + (size_t)layer * QKVN * D_ + D_ * D_;  lo = wql + (size_t)layer * QKVN * D_ + D_ * D_; }
        else if (grp == 2) { src = Wv + lsrc; hi = wqh + (size_t)layer * QKVN * D_ + 2*D_*D_;  lo = wql + (size_t)layer * QKVN * D_ + 2*D_*D_; }
        else               { src = Wo + lsrc; hi = woh + (size_t)layer * D_ * D_;              lo = wol + (size_t)layer * D_ * D_; }
        tsplit_tile(src, hi, lo, D_, D_, nt * 32, kt * 32, sc);
    } else if (grp == 4) {
        int nt = x & 63, kt = x >> 6;
        tsplit_tile(W1 + (size_t)layer * D_ * FF_,
                    w1h + (size_t)layer * FF_ * D_, w1l + (size_t)layer * FF_ * D_,
                    D_, FF_, nt * 32, kt * 32, 1.0f);
    } else if (grp == 5) {
        int nt = x & 15, kt = x >> 4;
        tsplit_tile(W2 + (size_t)layer * FF_ * D_,
                    w2h + (size_t)layer * D_ * FF_, w2l + (size_t)layer * D_ * FF_,
                    FF_, D_, nt * 32, kt * 32, 1.0f);
    } else {
        if (x >= 6) return;
        int idx = x * 256 + threadIdx.x;
        int n = idx;
        float v;
        if (n < D_)          v = bq[layer * D_ + n] * 0.125f;
        else if (n < 2 * D_) v = bk[layer * D_ + n - D_];
        else                 v = bv[layer * D_ + n - 2 * D_];
        bqkv[layer * QKVN + idx] = v;
    }
}

// ---------------- embedding ----------------
__global__ void embed_kernel(const int* __restrict__ tok, const float* __restrict__ gp,
                             const float* __restrict__ temb, const float* __restrict__ pemb,
                             float* __restrict__ x) {
    int idx = blockIdx.x * blockDim.x + threadIdx.x;
    int d  = idx & (D_ - 1);
    int bs = idx >> 9;
    int s  = bs % S_;
    int b  = bs / S_;
    float v;
    if (s == 0)            v = temb[(size_t)tok[b * T_] * D_ + d];
    else if (s <= NP_)     v = gp[((size_t)b * DG_) * NP_ * D_ + (s - 1) * D_ + d];
    else                   v = temb[(size_t)tok[b * T_ + (s - NP_)] * D_ + d];
    x[idx] = v + pemb[s * D_ + d];
}

// ---------------- layernorm, warp-per-row (+ fused prompt replace) ------------
__global__ void __launch_bounds__(256)
ln_split_kernel(float* __restrict__ x, const float* __restrict__ p, int bstride,
                const float* __restrict__ g, const float* __restrict__ bb,
                bf16* __restrict__ hi, bf16* __restrict__ lo) {
    int warp = threadIdx.x >> 5, lane = threadIdx.x & 31;
    int row = blockIdx.x * 8 + warp;
    if (row >= MROWS) return;
    int b = row / S_, s = row - b * S_;
    bool isp = (p != nullptr) && (s >= 1) && (s <= NP_);
    const float* srcrow = isp ? (p + (size_t)b * bstride + (size_t)(s - 1) * D_)
                              : (x + (size_t)row * D_);
    float4 v4[4];
    float su = 0.0f, ss = 0.0f;
    #pragma unroll
    for (int i = 0; i < 4; i++) {
        v4[i] = ((const float4*)srcrow)[lane + i * 32];
        su += v4[i].x + v4[i].y + v4[i].z + v4[i].w;
        ss += v4[i].x * v4[i].x + v4[i].y * v4[i].y + v4[i].z * v4[i].z + v4[i].w * v4[i].w;
    }
    if (isp) {
        #pragma unroll
        for (int i = 0; i < 4; i++)
            ((float4*)(x + (size_t)row * D_))[lane + i * 32] = v4[i];
    }
    #pragma unroll
    for (int o = 16; o > 0; o >>= 1) {
        su += __shfl_xor_sync(0xffffffffu, su, o);
        ss += __shfl_xor_sync(0xffffffffu, ss, o);
    }
    float mean = su * (1.0f / D_);
    float var  = ss * (1.0f / D_) - mean * mean;
    float rstd = rsqrtf(var + 1e-5f);
    #pragma unroll
    for (int i = 0; i < 4; i++) {
        float4 gv = ((const float4*)g)[lane + i * 32];
        float4 bv = ((const float4*)bb)[lane + i * 32];
        float o0 = (v4[i].x - mean) * rstd * gv.x + bv.x;
        float o1 = (v4[i].y - mean) * rstd * gv.y + bv.y;
        float o2 = (v4[i].z - mean) * rstd * gv.z + bv.z;
        float o3 = (v4[i].w - mean) * rstd * gv.w + bv.w;
        size_t o = (size_t)row * D_ + (lane + i * 32) * 4;
        __nv_bfloat162 h01 = __floats2bfloat162_rn(o0, o1);
        __nv_bfloat162 h23 = __floats2bfloat162_rn(o2, o3);
        *(__nv_bfloat162*)(hi + o)     = h01;
        *(__nv_bfloat162*)(hi + o + 2) = h23;
        float l0 = o0 - __low2float(h01);
        float l1 = o1 - __high2float(h01);
        float l2 = o2 - __low2float(h23);
        float l3 = o3 - __high2float(h23);
        *(__nv_bfloat162*)(lo + o)     = __floats2bfloat162_rn(l0, l1);
        *(__nv_bfloat162*)(lo + o + 2) = __floats2bfloat162_rn(l2, l3);
    }
}

// ---------------- shared epilogue ----------------
template<int MODE>
__device__ __forceinline__ void epi_write(float v0, float v1, size_t off, int c,
                                          const float* bias, const float* res,
                                          float* Cf, bf16* Chi, bf16* Clo) {
    v0 += bias[c]; v1 += bias[c + 1];
    if (MODE == 0) {
        *(float2*)(Cf + off) = make_float2(v0, v1);   // q-scale folded into weights
    } else if (MODE == 1) {
        float2 rr = *(const float2*)(res + off);
        *(float2*)(Cf + off) = make_float2(v0 + rr.x, v1 + rr.y);
    } else {
        v0 = v0 / (1.0f + __expf(-1.702f * v0));
        v1 = v1 / (1.0f + __expf(-1.702f * v1));
        __nv_bfloat162 h = __floats2bfloat162_rn(v0, v1);
        *(__nv_bfloat162*)(Chi + off) = h;
        float l0 = v0 - __low2float(h);
        float l1 = v1 - __high2float(h);
        *(__nv_bfloat162*)(Clo + off) = __floats2bfloat162_rn(l0, l1);
    }
}

// term-major MMA issue (round-6 exact), parameterized M-fragment count
#define MMA_TERMMAJOR(MF)                                                  \
    _Pragma("unroll")                                                      \
    for (int term = 0; term < 3; term++) {                                 \
        _Pragma("unroll")                                                  \
        for (int mf = 0; mf < MF; mf++) {                                  \
            _Pragma("unroll")                                              \
            for (int nf = 0; nf < 4; nf++) {                               \
                const uint32_t* a = (term == 2) ? aL[mf] : aH[mf];         \
                const uint32_t* b = (term == 1) ? &bL[nf >> 1][(nf & 1) * 2] \
                                                : &bH[nf >> 1][(nf & 1) * 2]; \
                mma16816(acc[mf][nf], a, b);                               \
            }                                                              \
        }                                                                  \
    }

// ---------------- GEMM A: 128x128 tile, 512 thr, 32x32 warp tiles, 3-stage ----
// (round-10 / round-6 best measured configuration, byte-for-byte)
constexpr int STAGE_A = 65536;
constexpr int SMEM_A_TOT = 3 * STAGE_A;     // 192KB

template<int MODE>
__global__ void __launch_bounds__(512)
gemm_mma128(const bf16* __restrict__ Ahi, const bf16* __restrict__ Alo,
            const bf16* __restrict__ Bhi, const bf16* __restrict__ Blo,
            const float* __restrict__ bias, const float* __restrict__ res,
            float* __restrict__ Cf, bf16* __restrict__ Chi, bf16* __restrict__ Clo,
            int N, int K) {
    extern __shared__ __align__(128) char smraw[];
    uint32_t sb = smem_u32(smraw);

    int tid = threadIdx.x, wid = tid >> 5, lane = tid & 31;
    int wm = wid >> 2, wn = wid & 3;
    int m0 = blockIdx.y * 128, n0 = blockIdx.x * 128;

    float acc[2][4][4];
    #pragma unroll
    for (int i = 0; i < 2; i++)
        #pragma unroll
        for (int j = 0; j < 4; j++)
            #pragma unroll
            for (int r = 0; r < 4; r++) acc[i][j][r] = 0.0f;

    const int nk = K >> 6;

    auto load_stage = [&](int buf, int kt2) {
        int k0 = kt2 << 6;
        uint32_t sb0 = sb + buf * STAGE_A;
        #pragma unroll
        for (int t = 0; t < 2; t++) {
            int idx = tid + t * 512;
            int row = idx >> 3, u = idx & 7;
            uint32_t so = sb0 + (row << 7) + ((u ^ (row & 7)) << 4);
            size_t ea = (size_t)(m0 + row) * K + k0 + u * 8;
            CP16(so,         Ahi + ea);
            CP16(so + 16384, Alo + ea);
        }
        #pragma unroll
        for (int t = 0; t < 2; t++) {
            int idx = tid + t * 512;
            int row = idx >> 3, u = idx & 7;
            uint32_t so = sb0 + 32768 + (row << 7) + ((u ^ (row & 7)) << 4);
            size_t eb = (size_t)(n0 + row) * K + k0 + u * 8;
            CP16(so,         Bhi + eb);
            CP16(so + 16384, Blo + eb);
        }
    };

    load_stage(0, 0); CP_COMMIT();
    load_stage(1, 1); CP_COMMIT();

    int lr = lane & 15, lu = lane >> 4;
    int bnn = wn * 32 + ((lane >> 4) << 3) + (lane & 7);
    int bus = (lane >> 3) & 1;

    for (int kt = 0; kt < nk; kt++) {
        if (kt < nk - 1) CP_WAIT1(); else CP_WAIT0();
        __syncthreads();
        if (kt + 2 < nk) { load_stage((kt + 2) % 3, kt + 2); CP_COMMIT(); }

        uint32_t base = sb + (kt % 3) * STAGE_A;
        #pragma unroll
        for (int kk = 0; kk < 4; kk++) {
            uint32_t aH[2][4], aL[2][4], bH[2][4], bL[2][4];
            #pragma unroll
            for (int mf = 0; mf < 2; mf++) {
                int r = wm * 32 + mf * 16 + lr;
                int u = kk * 2 + lu;
                uint32_t ad = base + (r << 7) + ((u ^ (r & 7)) << 4);
                ldsm4(aH[mf], ad);
                ldsm4(aL[mf], ad + 16384);
            }
            #pragma unroll
            for (int j = 0; j < 2; j++) {
                int n = bnn + j * 16;
                int u = kk * 2 + bus;
                uint32_t bd = base + 32768 + (n << 7) + ((u ^ (n & 7)) << 4);
                ldsm4(bH[j], bd);
                ldsm4(bL[j], bd + 16384);
            }
            MMA_TERMMAJOR(2);
        }
    }

    int r0b = m0 + wm * 32 + (lane >> 2);
    int cb  = n0 + wn * 32 + 2 * (lane & 3);
    #pragma unroll
    for (int mf = 0; mf < 2; mf++)
        #pragma unroll
        for (int nf = 0; nf < 4; nf++) {
            int c = cb + nf * 8;
            #pragma unroll
            for (int half = 0; half < 2; half++) {
                int r = r0b + mf * 16 + half * 8;
                size_t off = (size_t)r * N + c;
                epi_write<MODE>(acc[mf][nf][half * 2], acc[mf][nf][half * 2 + 1],
                                off, c, bias, res, Cf, Chi, Clo);
            }
        }
}

// ---------------- GEMM B: 128x64 tile, 256 threads, 2-stage, 2 CTAs/SM -------
// (round-6 best measured configuration, byte-for-byte)
constexpr int STAGE_B = 49152;
constexpr int SMEM_B_TOT = 2 * STAGE_B;     // 96KB -> 2 CTAs/SM

template<int MODE>
__global__ void __launch_bounds__(256, 2)
gemm_mma64(const bf16* __restrict__ Ahi, const bf16* __restrict__ Alo,
           const bf16* __restrict__ Bhi, const bf16* __restrict__ Blo,
           const float* __restrict__ bias, const float* __restrict__ res,
           float* __restrict__ Cf, bf16* __restrict__ Chi, bf16* __restrict__ Clo,
           int N, int K) {
    extern __shared__ __align__(128) char smraw[];
    uint32_t sb = smem_u32(smraw);

    int tid = threadIdx.x, wid = tid >> 5, lane = tid & 31;
    int wm = wid >> 1, wn = wid & 1;
    int m0 = blockIdx.y * 128, n0 = blockIdx.x * 64;

    float acc[2][4][4];
    #pragma unroll
    for (int i = 0; i < 2; i++)
        #pragma unroll
        for (int j = 0; j < 4; j++)
            #pragma unroll
            for (int r = 0; r < 4; r++) acc[i][j][r] = 0.0f;

    const int nk = K >> 6;

    auto load_stage = [&](int buf, int kt2) {
        int k0 = kt2 << 6;
        uint32_t sb0 = sb + buf * STAGE_B;
        #pragma unroll
        for (int t = 0; t < 4; t++) {
            int idx = tid + t * 256;
            int row = idx >> 3, u = idx & 7;
            uint32_t so = sb0 + (row << 7) + ((u ^ (row & 7)) << 4);
            size_t ea = (size_t)(m0 + row) * K + k0 + u * 8;
            CP16(so,         Ahi + ea);
            CP16(so + 16384, Alo + ea);
        }
        #pragma unroll
        for (int t = 0; t < 2; t++) {
            int idx = tid + t * 256;
            int row = idx >> 3, u = idx & 7;
            uint32_t so = sb0 + 32768 + (row << 7) + ((u ^ (row & 7)) << 4);
            size_t eb = (size_t)(n0 + row) * K + k0 + u * 8;
            CP16(so,        Bhi + eb);
            CP16(so + 8192, Blo + eb);
        }
    };

    load_stage(0, 0); CP_COMMIT();

    int lr = lane & 15, lu = lane >> 4;
    int bnn = wn * 32 + ((lane >> 4) << 3) + (lane & 7);
    int bus = (lane >> 3) & 1;

    for (int kt = 0; kt < nk; kt++) {
        CP_WAIT0();
        __syncthreads();
        if (kt + 1 < nk) { load_stage((kt + 1) & 1, kt + 1); CP_COMMIT(); }

        uint32_t base = sb + (kt & 1) * STAGE_B;
        #pragma unroll
        for (int kk = 0; kk < 4; kk++) {
            uint32_t aH[2][4], aL[2][4], bH[2][4], bL[2][4];
            #pragma unroll
            for (int mf = 0; mf < 2; mf++) {
                int r = wm * 32 + mf * 16 + lr;
                int u = kk * 2 + lu;
                uint32_t ad = base + (r << 7) + ((u ^ (r & 7)) << 4);
                ldsm4(aH[mf], ad);
                ldsm4(aL[mf], ad + 16384);
            }
            #pragma unroll
            for (int j = 0; j < 2; j++) {
                int n = bnn + j * 16;
                int u = kk * 2 + bus;
                uint32_t bd = base + 32768 + (n << 7) + ((u ^ (n & 7)) << 4);
                ldsm4(bH[j], bd);
                ldsm4(bL[j], bd + 8192);
            }
            MMA_TERMMAJOR(2);
        }
        __syncthreads();
    }

    int r0b = m0 + wm * 32 + (lane >> 2);
    int cb  = n0 + wn * 32 + 2 * (lane & 3);
    #pragma unroll
    for (int mf = 0; mf < 2; mf++)
        #pragma unroll
        for (int nf = 0; nf < 4; nf++) {
            int c = cb + nf * 8;
            #pragma unroll
            for (int half = 0; half < 2; half++) {
                int r = r0b + mf * 16 + half * 8;
                size_t off = (size_t)r * N + c;
                epi_write<MODE>(acc[mf][nf][half * 2], acc[mf][nf][half * 2 + 1],
                                off, c, bias, res, Cf, Chi, Clo);
            }
        }
}

// ---------------- fused attention: one block per (b, h), 512 threads ----------
// Round-16 structure; Q load vectorized to one float2 per lane (bit-identical).
constexpr int ATTN_KROW = DH_ + 4;   // 68 floats, float4-aligned rows
constexpr int ATTN_SMEM =
    (S_ * ATTN_KROW + S_ * DH_ + 16 * DH_ + 16 * 80) * 4 + S_ * 4;  // ~50.2 KB

__global__ void __launch_bounds__(512)
attn_kernel(const float* __restrict__ qkv, const int* __restrict__ amask,
            bf16* __restrict__ ohi, bf16* __restrict__ olo) {
    extern __shared__ __align__(16) float smf[];
    float* sK = smf;                            // [S_][68]
    float* sV = sK + S_ * ATTN_KROW;            // [S_][64]
    float* sQ = sV + S_ * DH_;                  // [16][64]
    float* sP = sQ + 16 * DH_;                  // [16][80]
    int*   sM = (int*)(sP + 16 * 80);           // [S_]
    int h = blockIdx.x, b = blockIdx.y;
    int tid = threadIdx.x, lane = tid & 31, w = tid >> 5;

    // vectorized K/V load: S_*DH_/4 = 1232 float4 transfers
    for (int i = tid; i < S_ * (DH_ / 4); i += 512) {
        int s = i >> 4, d4 = i & 15;
        size_t base4 = (((size_t)(b * S_ + s)) * QKVN + h * DH_) / 4 + d4;
        float4 kv = ((const float4*)qkv)[base4 + D_ / 4];
        float4 vv = ((const float4*)qkv)[base4 + 2 * D_ / 4];
        *(float4*)&sK[s * ATTN_KROW + d4 * 4] = kv;
        *(float4*)&sV[s * DH_ + d4 * 4]       = vv;
    }
    for (int i = tid; i < S_; i += 512)
        sM[i] = (i < NP_) ? 1 : amask[b * T_ + i - NP_];
    __syncthreads();

    float* sQw = sQ + w * DH_;
    float* sPw = sP + w * 80;

    for (int qi = w; qi < S_; qi += 16) {
        size_t qoff = ((size_t)(b * S_ + qi)) * QKVN + h * DH_;
        // one LDG.64 per lane (same values/positions as two scalar loads)
        float2 q2 = ((const float2*)(qkv + qoff))[lane];
        *(float2*)&sQw[lane * 2] = q2;
        __syncwarp();
        int nj = qi + 1;
        float sc[3];
        #pragma unroll
        for (int t = 0; t < 3; t++) {
            int j = lane + 32 * t;
            float dsum = -3.0e38f;
            if (j < nj) {
                dsum = 0.0f;
                const float* kr = sK + j * ATTN_KROW;
                #pragma unroll
                for (int d4 = 0; d4 < DH_ / 4; d4++) {
                    float4 qv = *(const float4*)&sQw[d4 * 4];
                    float4 kv = *(const float4*)&kr[d4 * 4];
                    dsum += qv.x * kv.x;
                    dsum += qv.y * kv.y;
                    dsum += qv.z * kv.z;
                    dsum += qv.w * kv.w;
                }
                if (sM[j] == 0) dsum = -1.0e30f;
            }
            sc[t] = dsum;
        }
        float m = fmaxf(sc[0], fmaxf(sc[1], sc[2]));
        #pragma unroll
        for (int o2 = 16; o2 > 0; o2 >>= 1) m = fmaxf(m, __shfl_xor_sync(0xffffffffu, m, o2));
        float e[3], esum = 0.0f;
        #pragma unroll
        for (int t = 0; t < 3; t++) {
            int j = lane + 32 * t;
            e[t] = (j < nj) ? __expf(sc[t] - m) : 0.0f;
            esum += e[t];
        }
        #pragma unroll
        for (int o2 = 16; o2 > 0; o2 >>= 1) esum += __shfl_xor_sync(0xffffffffu, esum, o2);
        float inv = 1.0f / esum;
        #pragma unroll
        for (int t = 0; t < 3; t++) {
            int j = lane + 32 * t;
            if (j < nj) sPw[j] = e[t] * inv;
        }
        __syncwarp();
        float a0 = 0.0f, a1 = 0.0f;
        int nj4 = nj & ~3;
        for (int j = 0; j < nj4; j += 4) {
            float4 p4 = *(const float4*)&sPw[j];
            a0 += p4.x * sV[j * DH_ + lane];       a1 += p4.x * sV[j * DH_ + lane + 32];
            a0 += p4.y * sV[(j + 1) * DH_ + lane]; a1 += p4.y * sV[(j + 1) * DH_ + lane + 32];
            a0 += p4.z * sV[(j + 2) * DH_ + lane]; a1 += p4.z * sV[(j + 2) * DH_ + lane + 32];
            a0 += p4.w * sV[(j + 3) * DH_ + lane]; a1 += p4.w * sV[(j + 3) * DH_ + lane + 32];
        }
        for (int j = nj4; j < nj; j++) {
            float p = sPw[j];
            a0 += p * sV[j * DH_ + lane];
            a1 += p * sV[j * DH_ + lane + 32];
        }
        size_t ooff = ((size_t)(b * S_ + qi)) * D_ + h * DH_;
        bf16 h0 = __float2bfloat16(a0);
        ohi[ooff + lane] = h0;
        olo[ooff + lane] = __float2bfloat16(a0 - __bfloat162float(h0));
        bf16 h1 = __float2bfloat16(a1);
        ohi[ooff + lane + 32] = h1;
        olo[ooff + lane + 32] = __float2bfloat16(a1 - __bfloat162float(h1));
        __syncwarp();
    }
}

// ---------------- final: argmax gather + layernorm -> out ----------------
__device__ __forceinline__ float2 block_sum2(float s, float ss) {
    __shared__ float sh1[4], sh2[4];
    int lane = threadIdx.x & 31, w = threadIdx.x >> 5;
    #pragma unroll
    for (int o = 16; o > 0; o >>= 1) {
        s  += __shfl_down_sync(0xffffffffu, s,  o);
        ss += __shfl_down_sync(0xffffffffu, ss, o);
    }
    if (lane == 0) { sh1[w] = s; sh2[w] = ss; }
    __syncthreads();
    return make_float2(sh1[0] + sh1[1] + sh1[2] + sh1[3],
                       sh2[0] + sh2[1] + sh2[2] + sh2[3]);
}

__global__ void __launch_bounds__(128)
final_kernel(const float* __restrict__ x, const int* __restrict__ tok,
             const float* __restrict__ g, const float* __restrict__ bb,
             float* __restrict__ out) {
    int b = blockIdx.x, tid = threadIdx.x;
    __shared__ int sval[128];
    __shared__ int srow;
    sval[tid] = (tid < T_) ? tok[b * T_ + tid] : (-2147483647 - 1);
    __syncthreads();
    if (tid == 0) {
        int best = sval[0], bi = 0;
        for (int t = 1; t < T_; t++)
            if (sval[t] > best) { best = sval[t]; bi = t; }
        srow = bi + NP_;
    }
    __syncthreads();
    int row = b * S_ + srow;
    float4 vv = ((const float4*)(x + (size_t)row * D_))[tid];
    float s  = vv.x + vv.y + vv.z + vv.w;
    float ss = vv.x * vv.x + vv.y * vv.y + vv.z * vv.z + vv.w * vv.w;
    float2 tot = block_sum2(s, ss);
    float mean = tot.x * (1.0f / D_);
    float var  = tot.y * (1.0f / D_) - mean * mean;
    float rstd = rsqrtf(var + 1e-5f);
    float4 gv = ((const float4*)g)[tid];
    float4 bv = ((const float4*)bb)[tid];
    float4 ov;
    ov.x = (vv.x - mean) * rstd * gv.x + bv.x;
    ov.y = (vv.y - mean) * rstd * gv.y + bv.y;
    ov.z = (vv.z - mean) * rstd * gv.z + bv.z;
    ov.w = (vv.w - mean) * rstd * gv.w + bv.w;
    ((float4*)(out + (size_t)b * D_))[tid] = ov;
}

// ---------------- launch ----------------
extern "C" void kernel_launch(void* const* d_in, const int* in_sizes, int n_in,
                              void* d_out, int out_size) {
    (void)in_sizes; (void)n_in; (void)out_size;
    const int*   tok   = (const int*)  d_in[0];
    const int*   amask = (const int*)  d_in[1];
    const float* gp    = (const float*)d_in[2];
    const float* sp    = (const float*)d_in[3];
    const float* temb  = (const float*)d_in[4];
    const float* pemb  = (const float*)d_in[5];
    const float* ln1g  = (const float*)d_in[6];
    const float* ln1b  = (const float*)d_in[7];
    const float* Wq    = (const float*)d_in[8];
    const float* bq    = (const float*)d_in[9];
    const float* Wk    = (const float*)d_in[10];
    const float* bk    = (const float*)d_in[11];
    const float* Wv    = (const float*)d_in[12];
    const float* bv    = (const float*)d_in[13];
    const float* Wo    = (const float*)d_in[14];
    const float* bo    = (const float*)d_in[15];
    const float* ln2g  = (const float*)d_in[16];
    const float* ln2b  = (const float*)d_in[17];
    const float* W1    = (const float*)d_in[18];
    const float* b1    = (const float*)d_in[19];
    const float* W2    = (const float*)d_in[20];
    const float* b2    = (const float*)d_in[21];
    const float* lnfg  = (const float*)d_in[22];
    const float* lnfb  = (const float*)d_in[23];
    float* out = (float*)d_out;

    float *x, *qkv, *bqkv;
    bf16 *hhi, *hlo, *ohi, *olo, *fhi, *flo;
    bf16 *wqh, *wql, *woh, *wol, *w1h, *w1l, *w2h, *w2l;
    cudaGetSymbolAddress((void**)&x,   g_x);
    cudaGetSymbolAddress((void**)&hhi, g_hhi);
    cudaGetSymbolAddress((void**)&hlo, g_hlo);
    cudaGetSymbolAddress((void**)&qkv, g_qkv);
    cudaGetSymbolAddress((void**)&ohi, g_ohi);
    cudaGetSymbolAddress((void**)&olo, g_olo);
    cudaGetSymbolAddress((void**)&fhi, g_fhi);
    cudaGetSymbolAddress((void**)&flo, g_flo);
    cudaGetSymbolAddress((void**)&wqh, w_qkv_hi);
    cudaGetSymbolAddress((void**)&wql, w_qkv_lo);
    cudaGetSymbolAddress((void**)&woh, w_o_hi);
    cudaGetSymbolAddress((void**)&wol, w_o_lo);
    cudaGetSymbolAddress((void**)&w1h, w_1_hi);
    cudaGetSymbolAddress((void**)&w1l, w_1_lo);
    cudaGetSymbolAddress((void**)&w2h, w_2_hi);
    cudaGetSymbolAddress((void**)&w2l, w_2_lo);
    cudaGetSymbolAddress((void**)&bqkv, g_bqkv);

    cudaFuncSetAttribute(gemm_mma128<0>, cudaFuncAttributeMaxDynamicSharedMemorySize, SMEM_A_TOT);
    cudaFuncSetAttribute(gemm_mma128<2>, cudaFuncAttributeMaxDynamicSharedMemorySize, SMEM_A_TOT);
    cudaFuncSetAttribute(gemm_mma64<1>,  cudaFuncAttributeMaxDynamicSharedMemorySize, SMEM_B_TOT);
    cudaFuncSetAttribute(attn_kernel,    cudaFuncAttributeMaxDynamicSharedMemorySize, ATTN_SMEM);

    prep_kernel<<<dim3(1024, 7, NL_), 256>>>(Wq, Wk, Wv, Wo, W1, W2, bq, bk, bv,
                                             wqh, wql, woh, wol, w1h, w1l, w2h, w2l, bqkv);
    embed_kernel<<<(B_ * S_ * D_) / 256, 256>>>(tok, gp, temb, pemb, x);

    dim3 gQKV(QKVN / 128, MROWS / 128);   // (12, 77)
    dim3 gFF (FF_  / 128, MROWS / 128);   // (16, 77)
    dim3 gD64(D_   / 64,  MROWS / 128);   // (8, 77) = 616 CTAs
    int lnGrid = MROWS / 8;               // 1232

    for (int i = 0; i < NL_; i++) {
        const float* p = nullptr; int bs = 0;
        if (i > 0) {
            if (i < DG_) { p = gp + (size_t)i * NP_ * D_;                 bs = DG_ * NP_ * D_; }
            else         { p = sp + (size_t)(i - (NL_ - DS_)) * NP_ * D_; bs = DS_ * NP_ * D_; }
        }
        ln_split_kernel<<<lnGrid, 256>>>(x, p, bs, ln1g + i * D_, ln1b + i * D_, hhi, hlo);
        gemm_mma128<0><<<gQKV, 512, SMEM_A_TOT>>>(hhi, hlo,
            wqh + (size_t)i * QKVN * D_, wql + (size_t)i * QKVN * D_,
            bqkv + i * QKVN, nullptr, qkv, nullptr, nullptr, QKVN, D_);
        attn_kernel<<<dim3(H_, B_), 512, ATTN_SMEM>>>(qkv, amask, ohi, olo);
        gemm_mma64<1><<<gD64, 256, SMEM_B_TOT>>>(ohi, olo,
            woh + (size_t)i * D_ * D_, wol + (size_t)i * D_ * D_,
            bo + i * D_, x, x, nullptr, nullptr, D_, D_);
        ln_split_kernel<<<lnGrid, 256>>>(x, nullptr, 0, ln2g + i * D_, ln2b + i * D_, hhi, hlo);
        gemm_mma128<2><<<gFF, 512, SMEM_A_TOT>>>(hhi, hlo,
            w1h + (size_t)i * FF_ * D_, w1l + (size_t)i * FF_ * D_,
            b1 + i * FF_, nullptr, nullptr, fhi, flo, FF_, D_);
        gemm_mma64<1><<<gD64, 256, SMEM_B_TOT>>>(fhi, flo,
            w2h + (size_t)i * D_ * FF_, w2l + (size_t)i * D_ * FF_,
            b2 + i * D_, x, x, nullptr, nullptr, D_, FF_);
    }
    final_kernel<<<B_, 128>>>(x, tok, lnfg, lnfb, out);
}